// round 2
// baseline (speedup 1.0000x reference)
#include <cuda_runtime.h>
#include <stdint.h>
#include <math.h>

#define NHEADS 8
#define HD     64
#define CCH    512
#define LSP    2304            // 48*48
#define BATCH  2
#define LWORDS (LSP/32)        // 72
#define LN_EPS 1e-5f

// ---------------- scratch (static device allocs are allowed) ----------------
__device__ float g_Q[BATCH*NHEADS*LSP*HD];   // (b,h,l,d)
__device__ float g_K[BATCH*NHEADS*LSP*HD];
__device__ float g_V[BATCH*NHEADS*LSP*HD];
__device__ float g_O[BATCH*CCH*LSP];         // attention out, (b,c,l)
__device__ float g_Y[BATCH*CCH*LSP];         // residual + Wo conv, (b,c,l)
__device__ unsigned g_maskbits[NHEADS*LSP*LWORDS];
__device__ int g_mask_mode;                  // 0=int32, 1=float32, 2=uint8

// ---------------- mask dtype detection ----------------
__global__ void detect_mask_kernel(const unsigned* __restrict__ mw) {
    __shared__ int s_f32, s_big;
    if (threadIdx.x == 0) { s_f32 = 0; s_big = 0; }
    __syncthreads();
    int lf = 0, lb = 0;
    for (int i = threadIdx.x; i < 4096; i += blockDim.x) {
        unsigned w = mw[i];
        if (w == 0x3F800000u) lf++;
        else if (w > 1u) lb++;
    }
    atomicAdd(&s_f32, lf);
    atomicAdd(&s_big, lb);
    __syncthreads();
    if (threadIdx.x == 0)
        g_mask_mode = (s_f32 > 0) ? 1 : ((s_big > 0) ? 2 : 0);
}

// ---------------- mask bit-packing ----------------
__global__ void pack_mask_kernel(const void* __restrict__ mask) {
    int w = blockIdx.x * blockDim.x + threadIdx.x;
    const int NW = NHEADS * LSP * LWORDS;
    if (w >= NW) return;
    size_t base = (size_t)w * 32;   // flat element index (mask is (1,8,L,L) row-major)
    int mode = g_mask_mode;
    unsigned bits = 0;
    if (mode == 0) {
        const int* p = (const int*)mask + base;
        #pragma unroll
        for (int i = 0; i < 32; i++) bits |= ((unsigned)(p[i] != 0)) << i;
    } else if (mode == 1) {
        const float* p = (const float*)mask + base;
        #pragma unroll
        for (int i = 0; i < 32; i++) bits |= ((unsigned)(p[i] != 0.0f)) << i;
    } else {
        const unsigned char* p = (const unsigned char*)mask + base;
        #pragma unroll
        for (int i = 0; i < 32; i++) bits |= ((unsigned)(p[i] != 0)) << i;
    }
    g_maskbits[w] = bits;
}

// ---------------- QKV projection GEMM (fused +pos, transposed output) -------
// grid (L/64, C/64, B*3), block 256.  C[m][n] = sum_c W[m][c]*(x[c][n]+pos[c][n]) + b[m]
__global__ void qkv_gemm_kernel(const float* __restrict__ x, const float* __restrict__ pos,
                                const float* __restrict__ Wq, const float* __restrict__ bq,
                                const float* __restrict__ Wk, const float* __restrict__ bk,
                                const float* __restrict__ Wv, const float* __restrict__ bv)
{
    int nt = blockIdx.x, mt = blockIdx.y;
    int b = blockIdx.z / 3, which = blockIdx.z % 3;
    const float* W    = (which == 0) ? Wq : (which == 1) ? Wk : Wv;
    const float* bias = (which == 0) ? bq : (which == 1) ? bk : bv;
    float* Out        = (which == 0) ? g_Q : (which == 1) ? g_K : g_V;

    __shared__ float As[16][68];   // [k][m]
    __shared__ float Bs[16][68];   // [k][n]
    __shared__ float Cs[64][68];   // staging transposed [n][m]

    int tid = threadIdx.x;
    int tx = tid & 15, ty = tid >> 4;
    float acc[4][4] = {};
    const float* xb = x + (size_t)b * CCH * LSP;

    for (int k0 = 0; k0 < CCH; k0 += 16) {
        {   // A: 64 rows (m) x 16 k, one float4 per thread along k, transposed store
            int r  = tid >> 2;
            int kq = (tid & 3) * 4;
            float4 a = *(const float4*)&W[(size_t)(mt * 64 + r) * CCH + k0 + kq];
            As[kq + 0][r] = a.x; As[kq + 1][r] = a.y;
            As[kq + 2][r] = a.z; As[kq + 3][r] = a.w;
        }
        {   // B: 16 rows (k) x 64 n, natural, fused + pos
            int kr = tid >> 4;
            int nq = (tid & 15) * 4;
            size_t off = (size_t)(k0 + kr) * LSP + nt * 64 + nq;
            float4 bv4 = *(const float4*)&xb[off];
            float4 pv  = *(const float4*)&pos[off];
            bv4.x += pv.x; bv4.y += pv.y; bv4.z += pv.z; bv4.w += pv.w;
            *(float4*)&Bs[kr][nq] = bv4;
        }
        __syncthreads();
        #pragma unroll
        for (int k = 0; k < 16; k++) {
            float av[4], bv2[4];
            *(float4*)av  = *(float4*)&As[k][ty * 4];
            *(float4*)bv2 = *(float4*)&Bs[k][tx * 4];
            #pragma unroll
            for (int r = 0; r < 4; r++)
                #pragma unroll
                for (int c = 0; c < 4; c++)
                    acc[r][c] += av[r] * bv2[c];
        }
        __syncthreads();
    }
    // epilogue: + bias, stage transposed [n][m]
    #pragma unroll
    for (int r = 0; r < 4; r++) {
        float bvv = bias[mt * 64 + 4 * ty + r];
        #pragma unroll
        for (int c = 0; c < 4; c++)
            Cs[4 * tx + c][4 * ty + r] = acc[r][c] + bvv;
    }
    __syncthreads();
    // write Out[((b*8+mt)*L + l)*64 + d]  (head == mt since HD==64)
    float* ob = Out + ((size_t)(b * NHEADS + mt) * LSP + nt * 64) * HD;
    #pragma unroll
    for (int it = 0; it < 4; it++) {
        int idx = tid + it * 256;          // 1024 float4s
        int nl = idx >> 4, seg = idx & 15;
        *(float4*)&ob[(size_t)nl * HD + seg * 4] = *(float4*)&Cs[nl][seg * 4];
    }
}

// ---------------- fused flash attention ----------------
// grid (L/64, B*heads), block 256, dynamic smem
__global__ void attn_kernel(const float* __restrict__ rel_table)
{
    extern __shared__ float sm[];
    float* Qs = sm;                 // [d][m]  64x68
    float* Ks = Qs + 64 * 68;       // [d][n]
    float* Vs = Ks + 64 * 68;       // [j][d]
    float* Ps = Vs + 64 * 68;       // [j][m]  (also output staging [d][m])
    float* relrow = Ps + 64 * 68;   // 65 (pad 68)
    unsigned* maskw = (unsigned*)(relrow + 68);  // [64][2]

    int tid = threadIdx.x;
    int tx = tid & 15, ty = tid >> 4;
    int bh = blockIdx.y;
    int b = bh / NHEADS, h = bh % NHEADS;
    int i0 = blockIdx.x * 64;

    const float* Qg = g_Q + (size_t)(b * NHEADS + h) * LSP * HD;
    const float* Kg = g_K + (size_t)(b * NHEADS + h) * LSP * HD;
    const float* Vg = g_V + (size_t)(b * NHEADS + h) * LSP * HD;
    const unsigned* mb = g_maskbits + (size_t)(h * LSP + i0) * LWORDS;

    if (tid < 65) relrow[tid] = rel_table[h * 65 + tid];
    // load Q tile transposed
    #pragma unroll
    for (int it = 0; it < 4; it++) {
        int idx = tid + it * 256;
        int m = idx >> 4, dq = (idx & 15) * 4;
        float4 q = *(const float4*)&Qg[(size_t)(i0 + m) * HD + dq];
        Qs[(dq + 0) * 68 + m] = q.x; Qs[(dq + 1) * 68 + m] = q.y;
        Qs[(dq + 2) * 68 + m] = q.z; Qs[(dq + 3) * 68 + m] = q.w;
    }

    float acc[4][4] = {};
    float mrow[4], lrow[4] = {};
    #pragma unroll
    for (int r = 0; r < 4; r++) mrow[r] = -INFINITY;
    const float scale = 0.125f;      // 1/sqrt(64)
    const int mwsel = tx >> 3;       // which word holds cols 4tx..4tx+3
    const int mwsh  = (tx * 4) & 31;

    for (int jt = 0; jt < 36; jt++) {
        int j0 = jt * 64;
        #pragma unroll
        for (int it = 0; it < 4; it++) {
            int idx = tid + it * 256;
            int n = idx >> 4, dq = (idx & 15) * 4;
            float4 kv = *(const float4*)&Kg[(size_t)(j0 + n) * HD + dq];
            Ks[(dq + 0) * 68 + n] = kv.x; Ks[(dq + 1) * 68 + n] = kv.y;
            Ks[(dq + 2) * 68 + n] = kv.z; Ks[(dq + 3) * 68 + n] = kv.w;
            float4 vv = *(const float4*)&Vg[(size_t)(j0 + n) * HD + dq];
            *(float4*)&Vs[n * 68 + dq] = vv;
        }
        if (tid < 128) {
            int r = tid >> 1, w = tid & 1;
            maskw[r * 2 + w] = mb[(size_t)r * LWORDS + jt * 2 + w];
        }
        __syncthreads();

        // S = Q K^T
        float s[4][4] = {};
        #pragma unroll 16
        for (int d = 0; d < 64; d++) {
            float av[4], bv2[4];
            *(float4*)av  = *(float4*)&Qs[d * 68 + ty * 4];
            *(float4*)bv2 = *(float4*)&Ks[d * 68 + tx * 4];
            #pragma unroll
            for (int r = 0; r < 4; r++)
                #pragma unroll
                for (int c = 0; c < 4; c++)
                    s[r][c] += av[r] * bv2[c];
        }
        // scale + rel bias + mask
        #pragma unroll
        for (int r = 0; r < 4; r++) {
            int i = i0 + 4 * ty + r;
            unsigned mwr = maskw[(4 * ty + r) * 2 + mwsel] >> mwsh;
            #pragma unroll
            for (int c = 0; c < 4; c++) {
                int j = j0 + 4 * tx + c;
                int dd = i - j;
                dd = min(max(dd, -32), 32);
                float sv = s[r][c] * scale + relrow[dd + 32];
                if (!((mwr >> c) & 1u)) sv = -1e9f;
                s[r][c] = sv;
            }
        }
        // row max (reduce across the 16 tx lanes sharing a row)
        float tmax[4];
        #pragma unroll
        for (int r = 0; r < 4; r++) {
            float v = fmaxf(fmaxf(s[r][0], s[r][1]), fmaxf(s[r][2], s[r][3]));
            #pragma unroll
            for (int off = 1; off < 16; off <<= 1)
                v = fmaxf(v, __shfl_xor_sync(0xffffffffu, v, off));
            tmax[r] = v;
        }
        float alpha[4], rsum[4];
        #pragma unroll
        for (int r = 0; r < 4; r++) {
            float nm = fmaxf(mrow[r], tmax[r]);
            alpha[r] = __expf(mrow[r] - nm);
            mrow[r] = nm;
            float ps = 0.f;
            #pragma unroll
            for (int c = 0; c < 4; c++) {
                float p = __expf(s[r][c] - nm);
                s[r][c] = p;
                ps += p;
            }
            #pragma unroll
            for (int off = 1; off < 16; off <<= 1)
                ps += __shfl_xor_sync(0xffffffffu, ps, off);
            rsum[r] = ps;
        }
        #pragma unroll
        for (int r = 0; r < 4; r++) {
            lrow[r] = lrow[r] * alpha[r] + rsum[r];
            #pragma unroll
            for (int c = 0; c < 4; c++) acc[r][c] *= alpha[r];
        }
        // P -> smem transposed [j][m]
        #pragma unroll
        for (int r = 0; r < 4; r++)
            #pragma unroll
            for (int c = 0; c < 4; c++)
                Ps[(4 * tx + c) * 68 + 4 * ty + r] = s[r][c];
        __syncthreads();
        // O += P V
        #pragma unroll 16
        for (int j = 0; j < 64; j++) {
            float pv[4], vv2[4];
            *(float4*)pv  = *(float4*)&Ps[j * 68 + ty * 4];
            *(float4*)vv2 = *(float4*)&Vs[j * 68 + tx * 4];
            #pragma unroll
            for (int r = 0; r < 4; r++)
                #pragma unroll
                for (int c = 0; c < 4; c++)
                    acc[r][c] += pv[r] * vv2[c];
        }
        __syncthreads();
    }
    // finalize: /l, stage transposed [d][m]
    #pragma unroll
    for (int r = 0; r < 4; r++) {
        float inv = 1.0f / lrow[r];
        #pragma unroll
        for (int c = 0; c < 4; c++)
            Ps[(4 * tx + c) * 68 + (4 * ty + r)] = acc[r][c] * inv;
    }
    __syncthreads();
    // write g_O[(b*512 + h*64 + d)*L + i0 + m], m contiguous -> coalesced
    float* Og = g_O + ((size_t)(b * CCH + h * HD)) * LSP + i0;
    #pragma unroll
    for (int it = 0; it < 4; it++) {
        int idx = tid + it * 256;
        int d = idx >> 4, seg = idx & 15;
        *(float4*)&Og[(size_t)d * LSP + seg * 4] = *(float4*)&Ps[d * 68 + seg * 4];
    }
}

// ---------------- output projection GEMM + bias + residual ----------------
// grid (L/64, C/64, B), block 256.  Y = x + Wo @ O + bo
__global__ void out_gemm_kernel(const float* __restrict__ x,
                                const float* __restrict__ Wo, const float* __restrict__ bo)
{
    int nt = blockIdx.x, mt = blockIdx.y, b = blockIdx.z;
    __shared__ float As[16][68];
    __shared__ float Bs[16][68];
    int tid = threadIdx.x;
    int tx = tid & 15, ty = tid >> 4;
    float acc[4][4] = {};
    const float* Ob = g_O + (size_t)b * CCH * LSP;

    for (int k0 = 0; k0 < CCH; k0 += 16) {
        {
            int r  = tid >> 2;
            int kq = (tid & 3) * 4;
            float4 a = *(const float4*)&Wo[(size_t)(mt * 64 + r) * CCH + k0 + kq];
            As[kq + 0][r] = a.x; As[kq + 1][r] = a.y;
            As[kq + 2][r] = a.z; As[kq + 3][r] = a.w;
        }
        {
            int kr = tid >> 4;
            int nq = (tid & 15) * 4;
            *(float4*)&Bs[kr][nq] =
                *(const float4*)&Ob[(size_t)(k0 + kr) * LSP + nt * 64 + nq];
        }
        __syncthreads();
        #pragma unroll
        for (int k = 0; k < 16; k++) {
            float av[4], bv2[4];
            *(float4*)av  = *(float4*)&As[k][ty * 4];
            *(float4*)bv2 = *(float4*)&Bs[k][tx * 4];
            #pragma unroll
            for (int r = 0; r < 4; r++)
                #pragma unroll
                for (int c = 0; c < 4; c++)
                    acc[r][c] += av[r] * bv2[c];
        }
        __syncthreads();
    }
    // epilogue: + bo + residual; direct coalesced write (n contiguous per row)
    #pragma unroll
    for (int r = 0; r < 4; r++) {
        int m = mt * 64 + 4 * ty + r;
        float bvv = bo[m];
        size_t off = ((size_t)b * CCH + m) * LSP + nt * 64 + 4 * tx;
        float4 xv = *(const float4*)&x[off];
        float4 res;
        res.x = acc[r][0] + bvv + xv.x;
        res.y = acc[r][1] + bvv + xv.y;
        res.z = acc[r][2] + bvv + xv.z;
        res.w = acc[r][3] + bvv + xv.w;
        *(float4*)&g_Y[off] = res;
    }
}

// ---------------- LayerNorm over channels ----------------
// grid B*L/32, block 256 (32 pixels x 8 channel groups)
__global__ void ln_kernel(const float* __restrict__ gamma, const float* __restrict__ beta,
                          float* __restrict__ out)
{
    int blk = blockIdx.x;
    int b  = blk / (LSP / 32);
    int l0 = (blk % (LSP / 32)) * 32;
    int lt = threadIdx.x & 31;
    int cg = threadIdx.x >> 5;   // 0..7
    const float* Yb = g_Y + (size_t)b * CCH * LSP;

    float sum = 0.f, sq = 0.f;
    for (int c = cg; c < CCH; c += 8) {
        float v = Yb[(size_t)c * LSP + l0 + lt];
        sum += v; sq += v * v;
    }
    __shared__ float ss[8][32], s2[8][32];
    __shared__ float mu[32], rs[32];
    ss[cg][lt] = sum; s2[cg][lt] = sq;
    __syncthreads();
    if (threadIdx.x < 32) {
        float s = 0.f, q = 0.f;
        #pragma unroll
        for (int g = 0; g < 8; g++) { s += ss[g][threadIdx.x]; q += s2[g][threadIdx.x]; }
        float m = s * (1.0f / CCH);
        float var = q * (1.0f / CCH) - m * m;
        mu[threadIdx.x] = m;
        rs[threadIdx.x] = rsqrtf(var + LN_EPS);
    }
    __syncthreads();
    float m = mu[lt], r = rs[lt];
    float* ob = out + (size_t)b * CCH * LSP;
    for (int c = cg; c < CCH; c += 8) {
        size_t off = (size_t)c * LSP + l0 + lt;
        ob[off] = (Yb[off] - m) * r * gamma[c] + beta[c];
    }
}

// ---------------- launch ----------------
extern "C" void kernel_launch(void* const* d_in, const int* in_sizes, int n_in,
                              void* d_out, int out_size)
{
    const float* x    = (const float*)d_in[0];
    const void*  mask =                d_in[1];
    const float* pos  = (const float*)d_in[2];
    const float* Wq   = (const float*)d_in[3];
    const float* bq   = (const float*)d_in[4];
    const float* Wk   = (const float*)d_in[5];
    const float* bk   = (const float*)d_in[6];
    const float* Wv   = (const float*)d_in[7];
    const float* bv   = (const float*)d_in[8];
    const float* Wo   = (const float*)d_in[9];
    const float* bo   = (const float*)d_in[10];
    const float* rel  = (const float*)d_in[11];
    const float* gam  = (const float*)d_in[12];
    const float* bet  = (const float*)d_in[13];
    float* out = (float*)d_out;

    const int attn_smem = (4 * 64 * 68 + 68) * 4 + 64 * 2 * 4;  // ~70.4 KB
    cudaFuncSetAttribute(attn_kernel, cudaFuncAttributeMaxDynamicSharedMemorySize, attn_smem);

    detect_mask_kernel<<<1, 256>>>((const unsigned*)mask);
    {
        const int NW = NHEADS * LSP * LWORDS;
        pack_mask_kernel<<<(NW + 255) / 256, 256>>>(mask);
    }
    qkv_gemm_kernel<<<dim3(LSP / 64, CCH / 64, BATCH * 3), 256>>>(
        x, pos, Wq, bq, Wk, bk, Wv, bv);
    attn_kernel<<<dim3(LSP / 64, BATCH * NHEADS), 256, attn_smem>>>(rel);
    out_gemm_kernel<<<dim3(LSP / 64, CCH / 64, BATCH), 256>>>(x, Wo, bo);
    ln_kernel<<<BATCH * LSP / 32, 256>>>(gam, bet, out);
}

// round 3
// speedup vs baseline: 1.6770x; 1.6770x over previous
#include <cuda_runtime.h>
#include <stdint.h>
#include <math.h>

#define NHEADS 8
#define HD     64
#define CCH    512
#define LSP    2304            // 48*48
#define BATCH  2
#define LWORDS (LSP/32)        // 72
#define LN_EPS 1e-5f

// ---------------- scratch ----------------
__device__ float g_Q[BATCH*NHEADS*LSP*HD];   // (b,h,l,d)
__device__ float g_K[BATCH*NHEADS*LSP*HD];
__device__ float g_V[BATCH*NHEADS*LSP*HD];
__device__ float g_O[BATCH*CCH*LSP];         // attention out, (b,c,l)
__device__ float g_Y[BATCH*CCH*LSP];         // residual + Wo conv, (b,c,l)
__device__ __align__(16) unsigned g_maskbits[NHEADS*LSP*LWORDS];
__device__ int g_mask_mode;

// ---------------- helpers ----------------
__device__ __forceinline__ float cvt_tf32(float x) {
    float r; asm("cvt.rna.tf32.f32 %0, %1;" : "=f"(r) : "f"(x)); return r;
}
__device__ __forceinline__ void mma_tf32(float& c0, float& c1, float& c2, float& c3,
                                         unsigned a0, unsigned a1, unsigned a2, unsigned a3,
                                         unsigned b0, unsigned b1) {
    asm volatile("mma.sync.aligned.m16n8k8.row.col.f32.tf32.tf32.f32 "
                 "{%0,%1,%2,%3},{%4,%5,%6,%7},{%8,%9},{%0,%1,%2,%3};"
                 : "+f"(c0), "+f"(c1), "+f"(c2), "+f"(c3)
                 : "r"(a0), "r"(a1), "r"(a2), "r"(a3), "r"(b0), "r"(b1));
}

// ---------------- mask dtype detection ----------------
__global__ void detect_mask_kernel(const unsigned* __restrict__ mw) {
    __shared__ int s_f32, s_big;
    if (threadIdx.x == 0) { s_f32 = 0; s_big = 0; }
    __syncthreads();
    int lf = 0, lb = 0;
    for (int i = threadIdx.x; i < 4096; i += blockDim.x) {
        unsigned w = mw[i];
        if (w == 0x3F800000u) lf++;
        else if (w > 1u) lb++;
    }
    atomicAdd(&s_f32, lf);
    atomicAdd(&s_big, lb);
    __syncthreads();
    if (threadIdx.x == 0)
        g_mask_mode = (s_f32 > 0) ? 1 : ((s_big > 0) ? 2 : 0);
}

// ---------------- mask bit-packing ----------------
__global__ void pack_mask_kernel(const void* __restrict__ mask) {
    int w = blockIdx.x * blockDim.x + threadIdx.x;
    const int NW = NHEADS * LSP * LWORDS;
    if (w >= NW) return;
    size_t base = (size_t)w * 32;
    int mode = g_mask_mode;
    unsigned bits = 0;
    if (mode == 0) {
        const int* p = (const int*)mask + base;
        #pragma unroll
        for (int i = 0; i < 32; i++) bits |= ((unsigned)(p[i] != 0)) << i;
    } else if (mode == 1) {
        const float* p = (const float*)mask + base;
        #pragma unroll
        for (int i = 0; i < 32; i++) bits |= ((unsigned)(p[i] != 0.0f)) << i;
    } else {
        const unsigned char* p = (const unsigned char*)mask + base;
        #pragma unroll
        for (int i = 0; i < 32; i++) bits |= ((unsigned)(p[i] != 0)) << i;
    }
    g_maskbits[w] = bits;
}

// ---------------- QKV projection GEMM (fused +pos, transposed output) -------
__global__ void qkv_gemm_kernel(const float* __restrict__ x, const float* __restrict__ pos,
                                const float* __restrict__ Wq, const float* __restrict__ bq,
                                const float* __restrict__ Wk, const float* __restrict__ bk,
                                const float* __restrict__ Wv, const float* __restrict__ bv)
{
    int nt = blockIdx.x, mt = blockIdx.y;
    int b = blockIdx.z / 3, which = blockIdx.z % 3;
    const float* W    = (which == 0) ? Wq : (which == 1) ? Wk : Wv;
    const float* bias = (which == 0) ? bq : (which == 1) ? bk : bv;
    float* Out        = (which == 0) ? g_Q : (which == 1) ? g_K : g_V;

    __shared__ float As[16][68];
    __shared__ float Bs[16][68];
    __shared__ float Cs[64][68];

    int tid = threadIdx.x;
    int tx = tid & 15, ty = tid >> 4;
    float acc[4][4] = {};
    const float* xb = x + (size_t)b * CCH * LSP;

    for (int k0 = 0; k0 < CCH; k0 += 16) {
        {
            int r  = tid >> 2;
            int kq = (tid & 3) * 4;
            float4 a = *(const float4*)&W[(size_t)(mt * 64 + r) * CCH + k0 + kq];
            As[kq + 0][r] = a.x; As[kq + 1][r] = a.y;
            As[kq + 2][r] = a.z; As[kq + 3][r] = a.w;
        }
        {
            int kr = tid >> 4;
            int nq = (tid & 15) * 4;
            size_t off = (size_t)(k0 + kr) * LSP + nt * 64 + nq;
            float4 bv4 = *(const float4*)&xb[off];
            float4 pv  = *(const float4*)&pos[off];
            bv4.x += pv.x; bv4.y += pv.y; bv4.z += pv.z; bv4.w += pv.w;
            *(float4*)&Bs[kr][nq] = bv4;
        }
        __syncthreads();
        #pragma unroll
        for (int k = 0; k < 16; k++) {
            float av[4], bv2[4];
            *(float4*)av  = *(float4*)&As[k][ty * 4];
            *(float4*)bv2 = *(float4*)&Bs[k][tx * 4];
            #pragma unroll
            for (int r = 0; r < 4; r++)
                #pragma unroll
                for (int c = 0; c < 4; c++)
                    acc[r][c] += av[r] * bv2[c];
        }
        __syncthreads();
    }
    #pragma unroll
    for (int r = 0; r < 4; r++) {
        float bvv = bias[mt * 64 + 4 * ty + r];
        #pragma unroll
        for (int c = 0; c < 4; c++)
            Cs[4 * tx + c][4 * ty + r] = acc[r][c] + bvv;
    }
    __syncthreads();
    float* ob = Out + ((size_t)(b * NHEADS + mt) * LSP + nt * 64) * HD;
    #pragma unroll
    for (int it = 0; it < 4; it++) {
        int idx = tid + it * 256;
        int nl = idx >> 4, seg = idx & 15;
        *(float4*)&ob[(size_t)nl * HD + seg * 4] = *(float4*)&Cs[nl][seg * 4];
    }
}

// ---------------- fused flash attention: mma.sync tf32 ----------------
// grid (36, 16), block 128 (4 warps; each warp owns 16 Q rows)
__global__ __launch_bounds__(128, 3)
void attn_kernel(const float* __restrict__ rel_table)
{
    extern __shared__ float sm[];
    float* Qs = sm;               // [64][68] tf32 (m,k); reused as Os[d][m] at end
    float* Ks = Qs + 64 * 68;     // [64][68] tf32 (j,d)
    float* Vs = Ks + 64 * 68;     // [64][72] tf32 (j,d)
    float* relrow = Vs + 64 * 72; // 68

    int tid = threadIdx.x;
    int w = tid >> 5, lane = tid & 31;
    int g = lane >> 2, q = lane & 3;
    int bh = blockIdx.y;
    int b = bh >> 3, h = bh & 7;
    int i0 = blockIdx.x * 64;

    const float* Qg = g_Q + (size_t)bh * LSP * HD;
    const float* Kg = g_K + (size_t)bh * LSP * HD;
    const float* Vg = g_V + (size_t)bh * LSP * HD;
    const unsigned* mbase = g_maskbits + (size_t)(h * LSP + i0) * LWORDS;

    if (tid < 65) relrow[tid] = rel_table[h * 65 + tid];

    // load Q tile -> Qs[m][k], tf32-rounded
    #pragma unroll
    for (int it = 0; it < 8; it++) {
        int idx = tid + it * 128;
        int m = idx >> 4, dq = (idx & 15) * 4;
        float4 v = *(const float4*)&Qg[(size_t)(i0 + m) * HD + dq];
        v.x = cvt_tf32(v.x); v.y = cvt_tf32(v.y);
        v.z = cvt_tf32(v.z); v.w = cvt_tf32(v.w);
        *(float4*)&Qs[m * 68 + dq] = v;
    }

    const int r0 = 16 * w + g;       // tile-local row (second row = r0+8)
    const int iA = i0 + r0, iB = iA + 8;
    float o[8][4] = {};
    float m0 = -INFINITY, m1 = -INFINITY, l0 = 0.f, l1 = 0.f;
    const float scale = 0.125f;
    const int lolane = (lane & ~3) | (q >> 1);
    const bool oddq = (q & 1);

    for (int jt = 0; jt < 36; jt++) {
        int j0 = jt * 64;
        __syncthreads();
        #pragma unroll
        for (int it = 0; it < 8; it++) {
            int idx = tid + it * 128;
            int n = idx >> 4, dq = (idx & 15) * 4;
            float4 kv = *(const float4*)&Kg[(size_t)(j0 + n) * HD + dq];
            kv.x = cvt_tf32(kv.x); kv.y = cvt_tf32(kv.y);
            kv.z = cvt_tf32(kv.z); kv.w = cvt_tf32(kv.w);
            *(float4*)&Ks[n * 68 + dq] = kv;
            float4 vv = *(const float4*)&Vg[(size_t)(j0 + n) * HD + dq];
            vv.x = cvt_tf32(vv.x); vv.y = cvt_tf32(vv.y);
            vv.z = cvt_tf32(vv.z); vv.w = cvt_tf32(vv.w);
            *(float4*)&Vs[n * 72 + dq] = vv;
        }
        __syncthreads();

        uint2 mwA = *(const uint2*)&mbase[(size_t)r0 * LWORDS + jt * 2];
        uint2 mwB = *(const uint2*)&mbase[(size_t)(r0 + 8) * LWORDS + jt * 2];

        // ---- S = Q K^T ----
        float sc[8][4];
        #pragma unroll
        for (int nb = 0; nb < 8; nb++)
            #pragma unroll
            for (int r = 0; r < 4; r++) sc[nb][r] = 0.f;

        #pragma unroll
        for (int kc = 0; kc < 8; kc++) {
            unsigned A0 = __float_as_uint(Qs[r0 * 68 + kc * 8 + q]);
            unsigned A1 = __float_as_uint(Qs[(r0 + 8) * 68 + kc * 8 + q]);
            unsigned A2 = __float_as_uint(Qs[r0 * 68 + kc * 8 + q + 4]);
            unsigned A3 = __float_as_uint(Qs[(r0 + 8) * 68 + kc * 8 + q + 4]);
            #pragma unroll
            for (int nb = 0; nb < 8; nb++) {
                unsigned B0 = __float_as_uint(Ks[(nb * 8 + g) * 68 + kc * 8 + q]);
                unsigned B1 = __float_as_uint(Ks[(nb * 8 + g) * 68 + kc * 8 + q + 4]);
                mma_tf32(sc[nb][0], sc[nb][1], sc[nb][2], sc[nb][3],
                         A0, A1, A2, A3, B0, B1);
            }
        }

        // ---- scale + rel bias + mask, row maxes ----
        float mx0 = -INFINITY, mx1 = -INFINITY;
        #pragma unroll
        for (int nb = 0; nb < 8; nb++) {
            int colt = nb * 8 + 2 * q;          // tile-local col (even)
            int jl = j0 + colt;
            unsigned wA = (colt >= 32) ? mwA.y : mwA.x;
            unsigned wB = (colt >= 32) ? mwB.y : mwB.x;
            int sh = colt & 31;
            {
                int d0 = min(max(iA - jl, -32), 32);
                int d1 = min(max(iA - jl - 1, -32), 32);
                float v0 = sc[nb][0] * scale + relrow[d0 + 32];
                float v1 = sc[nb][1] * scale + relrow[d1 + 32];
                if (!((wA >> sh) & 1u)) v0 = -1e9f;
                if (!((wA >> (sh + 1)) & 1u)) v1 = -1e9f;
                sc[nb][0] = v0; sc[nb][1] = v1;
                mx0 = fmaxf(mx0, fmaxf(v0, v1));
            }
            {
                int d0 = min(max(iB - jl, -32), 32);
                int d1 = min(max(iB - jl - 1, -32), 32);
                float v0 = sc[nb][2] * scale + relrow[d0 + 32];
                float v1 = sc[nb][3] * scale + relrow[d1 + 32];
                if (!((wB >> sh) & 1u)) v0 = -1e9f;
                if (!((wB >> (sh + 1)) & 1u)) v1 = -1e9f;
                sc[nb][2] = v0; sc[nb][3] = v1;
                mx1 = fmaxf(mx1, fmaxf(v0, v1));
            }
        }
        mx0 = fmaxf(mx0, __shfl_xor_sync(0xffffffffu, mx0, 1));
        mx0 = fmaxf(mx0, __shfl_xor_sync(0xffffffffu, mx0, 2));
        mx1 = fmaxf(mx1, __shfl_xor_sync(0xffffffffu, mx1, 1));
        mx1 = fmaxf(mx1, __shfl_xor_sync(0xffffffffu, mx1, 2));

        float nm0 = fmaxf(m0, mx0), nm1 = fmaxf(m1, mx1);
        float al0 = __expf(m0 - nm0), al1 = __expf(m1 - nm1);
        m0 = nm0; m1 = nm1;

        float s0 = 0.f, s1 = 0.f;
        #pragma unroll
        for (int nb = 0; nb < 8; nb++) {
            float p0 = __expf(sc[nb][0] - nm0);
            float p1 = __expf(sc[nb][1] - nm0);
            float p2 = __expf(sc[nb][2] - nm1);
            float p3 = __expf(sc[nb][3] - nm1);
            sc[nb][0] = p0; sc[nb][1] = p1; sc[nb][2] = p2; sc[nb][3] = p3;
            s0 += p0 + p1; s1 += p2 + p3;
        }
        s0 += __shfl_xor_sync(0xffffffffu, s0, 1);
        s0 += __shfl_xor_sync(0xffffffffu, s0, 2);
        s1 += __shfl_xor_sync(0xffffffffu, s1, 1);
        s1 += __shfl_xor_sync(0xffffffffu, s1, 2);
        l0 = l0 * al0 + s0; l1 = l1 * al1 + s1;

        #pragma unroll
        for (int db = 0; db < 8; db++) {
            o[db][0] *= al0; o[db][1] *= al0;
            o[db][2] *= al1; o[db][3] *= al1;
        }

        // ---- O += P V  (P C-frags -> A-frags via quad shuffles) ----
        #pragma unroll
        for (int kc = 0; kc < 8; kc++) {
            float x0 = __shfl_sync(0xffffffffu, sc[kc][0], lolane);
            float x1 = __shfl_sync(0xffffffffu, sc[kc][1], lolane);
            float x2 = __shfl_sync(0xffffffffu, sc[kc][2], lolane);
            float x3 = __shfl_sync(0xffffffffu, sc[kc][3], lolane);
            float y0 = __shfl_sync(0xffffffffu, sc[kc][0], lolane + 2);
            float y1 = __shfl_sync(0xffffffffu, sc[kc][1], lolane + 2);
            float y2 = __shfl_sync(0xffffffffu, sc[kc][2], lolane + 2);
            float y3 = __shfl_sync(0xffffffffu, sc[kc][3], lolane + 2);
            unsigned A0 = __float_as_uint(cvt_tf32(oddq ? x1 : x0));
            unsigned A1 = __float_as_uint(cvt_tf32(oddq ? x3 : x2));
            unsigned A2 = __float_as_uint(cvt_tf32(oddq ? y1 : y0));
            unsigned A3 = __float_as_uint(cvt_tf32(oddq ? y3 : y2));
            #pragma unroll
            for (int db = 0; db < 8; db++) {
                unsigned B0 = __float_as_uint(Vs[(kc * 8 + q) * 72 + db * 8 + g]);
                unsigned B1 = __float_as_uint(Vs[(kc * 8 + q + 4) * 72 + db * 8 + g]);
                mma_tf32(o[db][0], o[db][1], o[db][2], o[db][3],
                         A0, A1, A2, A3, B0, B1);
            }
        }
    }

    // ---- finalize: /l, stage into Qs as [d][m], coalesced write ----
    float inv0 = 1.0f / l0, inv1 = 1.0f / l1;
    __syncthreads();
    #pragma unroll
    for (int db = 0; db < 8; db++) {
        int d = db * 8 + 2 * q;
        Qs[(d    ) * 68 + r0    ] = o[db][0] * inv0;
        Qs[(d + 1) * 68 + r0    ] = o[db][1] * inv0;
        Qs[(d    ) * 68 + r0 + 8] = o[db][2] * inv1;
        Qs[(d + 1) * 68 + r0 + 8] = o[db][3] * inv1;
    }
    __syncthreads();
    float* Og = g_O + ((size_t)(b * CCH + h * HD)) * LSP + i0;
    #pragma unroll
    for (int it = 0; it < 8; it++) {
        int idx = tid + it * 128;
        int d = idx >> 4, seg = (idx & 15) * 4;
        *(float4*)&Og[(size_t)d * LSP + seg] = *(float4*)&Qs[d * 68 + seg];
    }
}

// ---------------- output projection GEMM + bias + residual ----------------
__global__ void out_gemm_kernel(const float* __restrict__ x,
                                const float* __restrict__ Wo, const float* __restrict__ bo)
{
    int nt = blockIdx.x, mt = blockIdx.y, b = blockIdx.z;
    __shared__ float As[16][68];
    __shared__ float Bs[16][68];
    int tid = threadIdx.x;
    int tx = tid & 15, ty = tid >> 4;
    float acc[4][4] = {};
    const float* Ob = g_O + (size_t)b * CCH * LSP;

    for (int k0 = 0; k0 < CCH; k0 += 16) {
        {
            int r  = tid >> 2;
            int kq = (tid & 3) * 4;
            float4 a = *(const float4*)&Wo[(size_t)(mt * 64 + r) * CCH + k0 + kq];
            As[kq + 0][r] = a.x; As[kq + 1][r] = a.y;
            As[kq + 2][r] = a.z; As[kq + 3][r] = a.w;
        }
        {
            int kr = tid >> 4;
            int nq = (tid & 15) * 4;
            *(float4*)&Bs[kr][nq] =
                *(const float4*)&Ob[(size_t)(k0 + kr) * LSP + nt * 64 + nq];
        }
        __syncthreads();
        #pragma unroll
        for (int k = 0; k < 16; k++) {
            float av[4], bv2[4];
            *(float4*)av  = *(float4*)&As[k][ty * 4];
            *(float4*)bv2 = *(float4*)&Bs[k][tx * 4];
            #pragma unroll
            for (int r = 0; r < 4; r++)
                #pragma unroll
                for (int c = 0; c < 4; c++)
                    acc[r][c] += av[r] * bv2[c];
        }
        __syncthreads();
    }
    #pragma unroll
    for (int r = 0; r < 4; r++) {
        int m = mt * 64 + 4 * ty + r;
        float bvv = bo[m];
        size_t off = ((size_t)b * CCH + m) * LSP + nt * 64 + 4 * tx;
        float4 xv = *(const float4*)&x[off];
        float4 res;
        res.x = acc[r][0] + bvv + xv.x;
        res.y = acc[r][1] + bvv + xv.y;
        res.z = acc[r][2] + bvv + xv.z;
        res.w = acc[r][3] + bvv + xv.w;
        *(float4*)&g_Y[off] = res;
    }
}

// ---------------- LayerNorm over channels ----------------
__global__ void ln_kernel(const float* __restrict__ gamma, const float* __restrict__ beta,
                          float* __restrict__ out)
{
    int blk = blockIdx.x;
    int b  = blk / (LSP / 32);
    int l0 = (blk % (LSP / 32)) * 32;
    int lt = threadIdx.x & 31;
    int cg = threadIdx.x >> 5;
    const float* Yb = g_Y + (size_t)b * CCH * LSP;

    float sum = 0.f, sq = 0.f;
    for (int c = cg; c < CCH; c += 8) {
        float v = Yb[(size_t)c * LSP + l0 + lt];
        sum += v; sq += v * v;
    }
    __shared__ float ss[8][32], s2[8][32];
    __shared__ float mu[32], rs[32];
    ss[cg][lt] = sum; s2[cg][lt] = sq;
    __syncthreads();
    if (threadIdx.x < 32) {
        float s = 0.f, qq = 0.f;
        #pragma unroll
        for (int gg = 0; gg < 8; gg++) { s += ss[gg][threadIdx.x]; qq += s2[gg][threadIdx.x]; }
        float m = s * (1.0f / CCH);
        float var = qq * (1.0f / CCH) - m * m;
        mu[threadIdx.x] = m;
        rs[threadIdx.x] = rsqrtf(var + LN_EPS);
    }
    __syncthreads();
    float m = mu[lt], r = rs[lt];
    float* ob = out + (size_t)b * CCH * LSP;
    for (int c = cg; c < CCH; c += 8) {
        size_t off = (size_t)c * LSP + l0 + lt;
        ob[off] = (Yb[off] - m) * r * gamma[c] + beta[c];
    }
}

// ---------------- launch ----------------
extern "C" void kernel_launch(void* const* d_in, const int* in_sizes, int n_in,
                              void* d_out, int out_size)
{
    const float* x    = (const float*)d_in[0];
    const void*  mask =                d_in[1];
    const float* pos  = (const float*)d_in[2];
    const float* Wq   = (const float*)d_in[3];
    const float* bq   = (const float*)d_in[4];
    const float* Wk   = (const float*)d_in[5];
    const float* bk   = (const float*)d_in[6];
    const float* Wv   = (const float*)d_in[7];
    const float* bv   = (const float*)d_in[8];
    const float* Wo   = (const float*)d_in[9];
    const float* bo   = (const float*)d_in[10];
    const float* rel  = (const float*)d_in[11];
    const float* gam  = (const float*)d_in[12];
    const float* bet  = (const float*)d_in[13];
    float* out = (float*)d_out;

    const int attn_smem = (64 * 68 + 64 * 68 + 64 * 72 + 68) * 4;  // 53520 B
    cudaFuncSetAttribute(attn_kernel, cudaFuncAttributeMaxDynamicSharedMemorySize, attn_smem);

    detect_mask_kernel<<<1, 256>>>((const unsigned*)mask);
    {
        const int NW = NHEADS * LSP * LWORDS;
        pack_mask_kernel<<<(NW + 255) / 256, 256>>>(mask);
    }
    qkv_gemm_kernel<<<dim3(LSP / 64, CCH / 64, BATCH * 3), 256>>>(
        x, pos, Wq, bq, Wk, bk, Wv, bv);
    attn_kernel<<<dim3(LSP / 64, BATCH * NHEADS), 128, attn_smem>>>(rel);
    out_gemm_kernel<<<dim3(LSP / 64, CCH / 64, BATCH), 256>>>(x, Wo, bo);
    ln_kernel<<<BATCH * LSP / 32, 256>>>(gam, bet, out);
}

// round 4
// speedup vs baseline: 2.2103x; 1.3180x over previous
#include <cuda_runtime.h>
#include <stdint.h>
#include <math.h>

#define NHEADS 8
#define HD     64
#define CCH    512
#define LSP    2304            // 48*48
#define BATCH  2
#define LWORDS (LSP/32)        // 72
#define LN_EPS 1e-5f

// ---------------- scratch ----------------
__device__ float g_Q[BATCH*NHEADS*LSP*HD];   // (b,h,l,d)
__device__ float g_K[BATCH*NHEADS*LSP*HD];
__device__ float g_V[BATCH*NHEADS*LSP*HD];
__device__ float g_O[BATCH*CCH*LSP];         // attention out, (b,c,l)
__device__ float g_Y[BATCH*CCH*LSP];         // residual + Wo conv, (b,c,l)
__device__ __align__(16) unsigned g_maskbits[NHEADS*LSP*LWORDS];
__device__ int g_mask_mode;

// ---------------- helpers ----------------
__device__ __forceinline__ float cvt_tf32(float x) {
    float r; asm("cvt.rna.tf32.f32 %0, %1;" : "=f"(r) : "f"(x)); return r;
}
__device__ __forceinline__ void mma_tf32(float& c0, float& c1, float& c2, float& c3,
                                         unsigned a0, unsigned a1, unsigned a2, unsigned a3,
                                         unsigned b0, unsigned b1) {
    asm volatile("mma.sync.aligned.m16n8k8.row.col.f32.tf32.tf32.f32 "
                 "{%0,%1,%2,%3},{%4,%5,%6,%7},{%8,%9},{%0,%1,%2,%3};"
                 : "+f"(c0), "+f"(c1), "+f"(c2), "+f"(c3)
                 : "r"(a0), "r"(a1), "r"(a2), "r"(a3), "r"(b0), "r"(b1));
}

// ---------------- mask dtype detection ----------------
__global__ void detect_mask_kernel(const unsigned* __restrict__ mw) {
    __shared__ int s_f32, s_big;
    if (threadIdx.x == 0) { s_f32 = 0; s_big = 0; }
    __syncthreads();
    int lf = 0, lb = 0;
    for (int i = threadIdx.x; i < 4096; i += blockDim.x) {
        unsigned w = mw[i];
        if (w == 0x3F800000u) lf++;
        else if (w > 1u) lb++;
    }
    atomicAdd(&s_f32, lf);
    atomicAdd(&s_big, lb);
    __syncthreads();
    if (threadIdx.x == 0)
        g_mask_mode = (s_f32 > 0) ? 1 : ((s_big > 0) ? 2 : 0);
}

// ---------------- mask bit-packing ----------------
__global__ void pack_mask_kernel(const void* __restrict__ mask) {
    int w = blockIdx.x * blockDim.x + threadIdx.x;
    const int NW = NHEADS * LSP * LWORDS;
    if (w >= NW) return;
    size_t base = (size_t)w * 32;
    int mode = g_mask_mode;
    unsigned bits = 0;
    if (mode == 0) {
        const int* p = (const int*)mask + base;
        #pragma unroll
        for (int i = 0; i < 32; i++) bits |= ((unsigned)(p[i] != 0)) << i;
    } else if (mode == 1) {
        const float* p = (const float*)mask + base;
        #pragma unroll
        for (int i = 0; i < 32; i++) bits |= ((unsigned)(p[i] != 0.0f)) << i;
    } else {
        const unsigned char* p = (const unsigned char*)mask + base;
        #pragma unroll
        for (int i = 0; i < 32; i++) bits |= ((unsigned)(p[i] != 0)) << i;
    }
    g_maskbits[w] = bits;
}

// ============== tf32 tensor-core GEMM kernels ==============
// Block tile 64(M) x 256(N), BK=16, 8 warps (wm 0..1 x wn 0..3), warp tile 32x64.
#define GAPAD 20
#define GBPAD 264
#define GASZ (64*GAPAD)     // 1280
#define GBSZ (16*GBPAD)     // 4224

// ---------------- QKV projection (tf32 mma, transposed output) ----------------
__global__ __launch_bounds__(256, 2)
void qkv_gemm_kernel(const float* __restrict__ x, const float* __restrict__ pos,
                     const float* __restrict__ Wq, const float* __restrict__ bq,
                     const float* __restrict__ Wk, const float* __restrict__ bk,
                     const float* __restrict__ Wv, const float* __restrict__ bv)
{
    __shared__ float sm[2 * (GASZ + GBSZ)];    // 44 KB

    int nt = blockIdx.x;                 // 0..8
    int mt = blockIdx.y;                 // 0..7 (head)
    int bz = blockIdx.z;
    int b = bz / 3, which = bz % 3;
    const float* W    = (which == 0) ? Wq : (which == 1) ? Wk : Wv;
    const float* bias = (which == 0) ? bq : (which == 1) ? bk : bv;
    float* Out        = (which == 0) ? g_Q : (which == 1) ? g_K : g_V;

    int n0 = nt * 256;
    const float* xb = x + (size_t)b * CCH * LSP;

    int tid = threadIdx.x;
    int w = tid >> 5, lane = tid & 31;
    int wm = w >> 2, wn = w & 3;
    int g = lane >> 2, q = lane & 3;

    int ar = tid >> 2, akq = (tid & 3) << 2;
    const float* Wrow = W + (size_t)(mt * 64 + ar) * CCH + akq;

    float acc[2][8][4];
    #pragma unroll
    for (int mi = 0; mi < 2; mi++)
        #pragma unroll
        for (int ni = 0; ni < 8; ni++)
            #pragma unroll
            for (int r = 0; r < 4; r++) acc[mi][ni][r] = 0.f;

    float4 aR; float4 bR[4];
    // prologue load k0 = 0
    aR = *(const float4*)&Wrow[0];
    #pragma unroll
    for (int i = 0; i < 4; i++) {
        int idx = tid + i * 256;
        int kr = idx >> 6, nq = (idx & 63) << 2;
        size_t off = (size_t)kr * LSP + n0 + nq;
        float4 v = *(const float4*)&xb[off];
        float4 p = *(const float4*)&pos[off];
        v.x += p.x; v.y += p.y; v.z += p.z; v.w += p.w;
        bR[i] = v;
    }
    {
        float* as = sm;
        float* bs = sm + 2 * GASZ;
        as[ar * GAPAD + akq + 0] = cvt_tf32(aR.x);
        as[ar * GAPAD + akq + 1] = cvt_tf32(aR.y);
        as[ar * GAPAD + akq + 2] = cvt_tf32(aR.z);
        as[ar * GAPAD + akq + 3] = cvt_tf32(aR.w);
        #pragma unroll
        for (int i = 0; i < 4; i++) {
            int idx = tid + i * 256;
            int kr = idx >> 6, nq = (idx & 63) << 2;
            bs[kr * GBPAD + nq + 0] = cvt_tf32(bR[i].x);
            bs[kr * GBPAD + nq + 1] = cvt_tf32(bR[i].y);
            bs[kr * GBPAD + nq + 2] = cvt_tf32(bR[i].z);
            bs[kr * GBPAD + nq + 3] = cvt_tf32(bR[i].w);
        }
    }
    __syncthreads();

    int buf = 0;
    for (int kt = 0; kt < 32; kt++) {
        if (kt < 31) {
            int k0 = (kt + 1) * 16;
            aR = *(const float4*)&Wrow[k0];
            #pragma unroll
            for (int i = 0; i < 4; i++) {
                int idx = tid + i * 256;
                int kr = idx >> 6, nq = (idx & 63) << 2;
                size_t off = (size_t)(k0 + kr) * LSP + n0 + nq;
                float4 v = *(const float4*)&xb[off];
                float4 p = *(const float4*)&pos[off];
                v.x += p.x; v.y += p.y; v.z += p.z; v.w += p.w;
                bR[i] = v;
            }
        }
        const float* as = sm + buf * GASZ;
        const float* bs = sm + 2 * GASZ + buf * GBSZ;
        #pragma unroll
        for (int kc = 0; kc < 2; kc++) {
            unsigned Af[2][4];
            #pragma unroll
            for (int mi = 0; mi < 2; mi++) {
                int mr = wm * 32 + mi * 16;
                Af[mi][0] = __float_as_uint(as[(mr + g    ) * GAPAD + kc * 8 + q    ]);
                Af[mi][1] = __float_as_uint(as[(mr + g + 8) * GAPAD + kc * 8 + q    ]);
                Af[mi][2] = __float_as_uint(as[(mr + g    ) * GAPAD + kc * 8 + q + 4]);
                Af[mi][3] = __float_as_uint(as[(mr + g + 8) * GAPAD + kc * 8 + q + 4]);
            }
            #pragma unroll
            for (int ni = 0; ni < 8; ni++) {
                unsigned B0 = __float_as_uint(bs[(kc * 8 + q    ) * GBPAD + wn * 64 + ni * 8 + g]);
                unsigned B1 = __float_as_uint(bs[(kc * 8 + q + 4) * GBPAD + wn * 64 + ni * 8 + g]);
                mma_tf32(acc[0][ni][0], acc[0][ni][1], acc[0][ni][2], acc[0][ni][3],
                         Af[0][0], Af[0][1], Af[0][2], Af[0][3], B0, B1);
                mma_tf32(acc[1][ni][0], acc[1][ni][1], acc[1][ni][2], acc[1][ni][3],
                         Af[1][0], Af[1][1], Af[1][2], Af[1][3], B0, B1);
            }
        }
        if (kt < 31) {
            float* asn = sm + (buf ^ 1) * GASZ;
            float* bsn = sm + 2 * GASZ + (buf ^ 1) * GBSZ;
            asn[ar * GAPAD + akq + 0] = cvt_tf32(aR.x);
            asn[ar * GAPAD + akq + 1] = cvt_tf32(aR.y);
            asn[ar * GAPAD + akq + 2] = cvt_tf32(aR.z);
            asn[ar * GAPAD + akq + 3] = cvt_tf32(aR.w);
            #pragma unroll
            for (int i = 0; i < 4; i++) {
                int idx = tid + i * 256;
                int kr = idx >> 6, nq = (idx & 63) << 2;
                bsn[kr * GBPAD + nq + 0] = cvt_tf32(bR[i].x);
                bsn[kr * GBPAD + nq + 1] = cvt_tf32(bR[i].y);
                bsn[kr * GBPAD + nq + 2] = cvt_tf32(bR[i].z);
                bsn[kr * GBPAD + nq + 3] = cvt_tf32(bR[i].w);
            }
        }
        __syncthreads();
        buf ^= 1;
    }

    // epilogue: + bias, stage [n][m] per 64-col chunk, coalesced transposed write
    float bb[2][2];
    #pragma unroll
    for (int mi = 0; mi < 2; mi++) {
        bb[mi][0] = bias[mt * 64 + wm * 32 + mi * 16 + g];
        bb[mi][1] = bias[mt * 64 + wm * 32 + mi * 16 + g + 8];
    }
    float* Cs = sm;   // [64][68]
    float* ob = Out + ((size_t)(b * NHEADS + mt) * LSP + n0) * HD;
    #pragma unroll
    for (int chunk = 0; chunk < 4; chunk++) {
        if (wn == chunk) {
            #pragma unroll
            for (int mi = 0; mi < 2; mi++) {
                int m0 = wm * 32 + mi * 16 + g;
                #pragma unroll
                for (int ni = 0; ni < 8; ni++) {
                    int col = ni * 8 + 2 * q;
                    Cs[(col    ) * 68 + m0    ] = acc[mi][ni][0] + bb[mi][0];
                    Cs[(col + 1) * 68 + m0    ] = acc[mi][ni][1] + bb[mi][0];
                    Cs[(col    ) * 68 + m0 + 8] = acc[mi][ni][2] + bb[mi][1];
                    Cs[(col + 1) * 68 + m0 + 8] = acc[mi][ni][3] + bb[mi][1];
                }
            }
        }
        __syncthreads();
        #pragma unroll
        for (int i = 0; i < 4; i++) {
            int idx = tid + i * 256;
            int l = idx >> 4, mseg = (idx & 15) << 2;
            *(float4*)&ob[(size_t)(chunk * 64 + l) * HD + mseg] = *(float4*)&Cs[l * 68 + mseg];
        }
        __syncthreads();
    }
}

// ---------------- output projection (tf32 mma) + bias + residual ----------------
__global__ __launch_bounds__(256, 2)
void out_gemm_kernel(const float* __restrict__ x,
                     const float* __restrict__ Wo, const float* __restrict__ bo)
{
    __shared__ float sm[2 * (GASZ + GBSZ)];

    int nt = blockIdx.x;      // 0..8
    int mt = blockIdx.y;      // 0..7
    int b  = blockIdx.z;      // 0..1
    int n0 = nt * 256;
    const float* Ob = g_O + (size_t)b * CCH * LSP;

    int tid = threadIdx.x;
    int w = tid >> 5, lane = tid & 31;
    int wm = w >> 2, wn = w & 3;
    int g = lane >> 2, q = lane & 3;

    int ar = tid >> 2, akq = (tid & 3) << 2;
    const float* Wrow = Wo + (size_t)(mt * 64 + ar) * CCH + akq;

    float acc[2][8][4];
    #pragma unroll
    for (int mi = 0; mi < 2; mi++)
        #pragma unroll
        for (int ni = 0; ni < 8; ni++)
            #pragma unroll
            for (int r = 0; r < 4; r++) acc[mi][ni][r] = 0.f;

    float4 aR; float4 bR[4];
    aR = *(const float4*)&Wrow[0];
    #pragma unroll
    for (int i = 0; i < 4; i++) {
        int idx = tid + i * 256;
        int kr = idx >> 6, nq = (idx & 63) << 2;
        bR[i] = *(const float4*)&Ob[(size_t)kr * LSP + n0 + nq];
    }
    {
        float* as = sm;
        float* bs = sm + 2 * GASZ;
        as[ar * GAPAD + akq + 0] = cvt_tf32(aR.x);
        as[ar * GAPAD + akq + 1] = cvt_tf32(aR.y);
        as[ar * GAPAD + akq + 2] = cvt_tf32(aR.z);
        as[ar * GAPAD + akq + 3] = cvt_tf32(aR.w);
        #pragma unroll
        for (int i = 0; i < 4; i++) {
            int idx = tid + i * 256;
            int kr = idx >> 6, nq = (idx & 63) << 2;
            bs[kr * GBPAD + nq + 0] = cvt_tf32(bR[i].x);
            bs[kr * GBPAD + nq + 1] = cvt_tf32(bR[i].y);
            bs[kr * GBPAD + nq + 2] = cvt_tf32(bR[i].z);
            bs[kr * GBPAD + nq + 3] = cvt_tf32(bR[i].w);
        }
    }
    __syncthreads();

    int buf = 0;
    for (int kt = 0; kt < 32; kt++) {
        if (kt < 31) {
            int k0 = (kt + 1) * 16;
            aR = *(const float4*)&Wrow[k0];
            #pragma unroll
            for (int i = 0; i < 4; i++) {
                int idx = tid + i * 256;
                int kr = idx >> 6, nq = (idx & 63) << 2;
                bR[i] = *(const float4*)&Ob[(size_t)(k0 + kr) * LSP + n0 + nq];
            }
        }
        const float* as = sm + buf * GASZ;
        const float* bs = sm + 2 * GASZ + buf * GBSZ;
        #pragma unroll
        for (int kc = 0; kc < 2; kc++) {
            unsigned Af[2][4];
            #pragma unroll
            for (int mi = 0; mi < 2; mi++) {
                int mr = wm * 32 + mi * 16;
                Af[mi][0] = __float_as_uint(as[(mr + g    ) * GAPAD + kc * 8 + q    ]);
                Af[mi][1] = __float_as_uint(as[(mr + g + 8) * GAPAD + kc * 8 + q    ]);
                Af[mi][2] = __float_as_uint(as[(mr + g    ) * GAPAD + kc * 8 + q + 4]);
                Af[mi][3] = __float_as_uint(as[(mr + g + 8) * GAPAD + kc * 8 + q + 4]);
            }
            #pragma unroll
            for (int ni = 0; ni < 8; ni++) {
                unsigned B0 = __float_as_uint(bs[(kc * 8 + q    ) * GBPAD + wn * 64 + ni * 8 + g]);
                unsigned B1 = __float_as_uint(bs[(kc * 8 + q + 4) * GBPAD + wn * 64 + ni * 8 + g]);
                mma_tf32(acc[0][ni][0], acc[0][ni][1], acc[0][ni][2], acc[0][ni][3],
                         Af[0][0], Af[0][1], Af[0][2], Af[0][3], B0, B1);
                mma_tf32(acc[1][ni][0], acc[1][ni][1], acc[1][ni][2], acc[1][ni][3],
                         Af[1][0], Af[1][1], Af[1][2], Af[1][3], B0, B1);
            }
        }
        if (kt < 31) {
            float* asn = sm + (buf ^ 1) * GASZ;
            float* bsn = sm + 2 * GASZ + (buf ^ 1) * GBSZ;
            asn[ar * GAPAD + akq + 0] = cvt_tf32(aR.x);
            asn[ar * GAPAD + akq + 1] = cvt_tf32(aR.y);
            asn[ar * GAPAD + akq + 2] = cvt_tf32(aR.z);
            asn[ar * GAPAD + akq + 3] = cvt_tf32(aR.w);
            #pragma unroll
            for (int i = 0; i < 4; i++) {
                int idx = tid + i * 256;
                int kr = idx >> 6, nq = (idx & 63) << 2;
                bsn[kr * GBPAD + nq + 0] = cvt_tf32(bR[i].x);
                bsn[kr * GBPAD + nq + 1] = cvt_tf32(bR[i].y);
                bsn[kr * GBPAD + nq + 2] = cvt_tf32(bR[i].z);
                bsn[kr * GBPAD + nq + 3] = cvt_tf32(bR[i].w);
            }
        }
        __syncthreads();
        buf ^= 1;
    }

    // epilogue: + bo + residual, direct float2 stores
    #pragma unroll
    for (int mi = 0; mi < 2; mi++) {
        int m0 = mt * 64 + wm * 32 + mi * 16 + g;
        float b0v = bo[m0], b1v = bo[m0 + 8];
        #pragma unroll
        for (int ni = 0; ni < 8; ni++) {
            int n = n0 + wn * 64 + ni * 8 + 2 * q;
            size_t off0 = ((size_t)b * CCH + m0) * LSP + n;
            size_t off1 = off0 + (size_t)8 * LSP;
            float2 xv0 = *(const float2*)&x[off0];
            float2 xv1 = *(const float2*)&x[off1];
            float2 r0 = { acc[mi][ni][0] + b0v + xv0.x, acc[mi][ni][1] + b0v + xv0.y };
            float2 r1 = { acc[mi][ni][2] + b1v + xv1.x, acc[mi][ni][3] + b1v + xv1.y };
            *(float2*)&g_Y[off0] = r0;
            *(float2*)&g_Y[off1] = r1;
        }
    }
}

// ---------------- fused flash attention: mma.sync tf32 ----------------
__global__ __launch_bounds__(128, 3)
void attn_kernel(const float* __restrict__ rel_table)
{
    extern __shared__ float smx[];
    float* Qs = smx;              // [64][68]
    float* Ks = Qs + 64 * 68;     // [64][68]
    float* Vs = Ks + 64 * 68;     // [64][72]
    float* relrow = Vs + 64 * 72; // 68

    int tid = threadIdx.x;
    int w = tid >> 5, lane = tid & 31;
    int g = lane >> 2, q = lane & 3;
    int bh = blockIdx.y;
    int b = bh >> 3, h = bh & 7;
    int i0 = blockIdx.x * 64;

    const float* Qg = g_Q + (size_t)bh * LSP * HD;
    const float* Kg = g_K + (size_t)bh * LSP * HD;
    const float* Vg = g_V + (size_t)bh * LSP * HD;
    const unsigned* mbase = g_maskbits + (size_t)(h * LSP + i0) * LWORDS;

    if (tid < 65) relrow[tid] = rel_table[h * 65 + tid];

    #pragma unroll
    for (int it = 0; it < 8; it++) {
        int idx = tid + it * 128;
        int m = idx >> 4, dq = (idx & 15) * 4;
        float4 v = *(const float4*)&Qg[(size_t)(i0 + m) * HD + dq];
        v.x = cvt_tf32(v.x); v.y = cvt_tf32(v.y);
        v.z = cvt_tf32(v.z); v.w = cvt_tf32(v.w);
        *(float4*)&Qs[m * 68 + dq] = v;
    }

    const int r0 = 16 * w + g;
    const int iA = i0 + r0, iB = iA + 8;
    float o[8][4] = {};
    float m0 = -INFINITY, m1 = -INFINITY, l0 = 0.f, l1 = 0.f;
    const float scale = 0.125f;
    const int lolane = (lane & ~3) | (q >> 1);
    const bool oddq = (q & 1);

    for (int jt = 0; jt < 36; jt++) {
        int j0 = jt * 64;
        __syncthreads();
        #pragma unroll
        for (int it = 0; it < 8; it++) {
            int idx = tid + it * 128;
            int n = idx >> 4, dq = (idx & 15) * 4;
            float4 kv = *(const float4*)&Kg[(size_t)(j0 + n) * HD + dq];
            kv.x = cvt_tf32(kv.x); kv.y = cvt_tf32(kv.y);
            kv.z = cvt_tf32(kv.z); kv.w = cvt_tf32(kv.w);
            *(float4*)&Ks[n * 68 + dq] = kv;
            float4 vv = *(const float4*)&Vg[(size_t)(j0 + n) * HD + dq];
            vv.x = cvt_tf32(vv.x); vv.y = cvt_tf32(vv.y);
            vv.z = cvt_tf32(vv.z); vv.w = cvt_tf32(vv.w);
            *(float4*)&Vs[n * 72 + dq] = vv;
        }
        __syncthreads();

        uint2 mwA = *(const uint2*)&mbase[(size_t)r0 * LWORDS + jt * 2];
        uint2 mwB = *(const uint2*)&mbase[(size_t)(r0 + 8) * LWORDS + jt * 2];

        float sc[8][4];
        #pragma unroll
        for (int nb = 0; nb < 8; nb++)
            #pragma unroll
            for (int r = 0; r < 4; r++) sc[nb][r] = 0.f;

        #pragma unroll
        for (int kc = 0; kc < 8; kc++) {
            unsigned A0 = __float_as_uint(Qs[r0 * 68 + kc * 8 + q]);
            unsigned A1 = __float_as_uint(Qs[(r0 + 8) * 68 + kc * 8 + q]);
            unsigned A2 = __float_as_uint(Qs[r0 * 68 + kc * 8 + q + 4]);
            unsigned A3 = __float_as_uint(Qs[(r0 + 8) * 68 + kc * 8 + q + 4]);
            #pragma unroll
            for (int nb = 0; nb < 8; nb++) {
                unsigned B0 = __float_as_uint(Ks[(nb * 8 + g) * 68 + kc * 8 + q]);
                unsigned B1 = __float_as_uint(Ks[(nb * 8 + g) * 68 + kc * 8 + q + 4]);
                mma_tf32(sc[nb][0], sc[nb][1], sc[nb][2], sc[nb][3],
                         A0, A1, A2, A3, B0, B1);
            }
        }

        float mx0 = -INFINITY, mx1 = -INFINITY;
        #pragma unroll
        for (int nb = 0; nb < 8; nb++) {
            int colt = nb * 8 + 2 * q;
            int jl = j0 + colt;
            unsigned wA = (colt >= 32) ? mwA.y : mwA.x;
            unsigned wB = (colt >= 32) ? mwB.y : mwB.x;
            int sh = colt & 31;
            {
                int d0 = min(max(iA - jl, -32), 32);
                int d1 = min(max(iA - jl - 1, -32), 32);
                float v0 = sc[nb][0] * scale + relrow[d0 + 32];
                float v1 = sc[nb][1] * scale + relrow[d1 + 32];
                if (!((wA >> sh) & 1u)) v0 = -1e9f;
                if (!((wA >> (sh + 1)) & 1u)) v1 = -1e9f;
                sc[nb][0] = v0; sc[nb][1] = v1;
                mx0 = fmaxf(mx0, fmaxf(v0, v1));
            }
            {
                int d0 = min(max(iB - jl, -32), 32);
                int d1 = min(max(iB - jl - 1, -32), 32);
                float v0 = sc[nb][2] * scale + relrow[d0 + 32];
                float v1 = sc[nb][3] * scale + relrow[d1 + 32];
                if (!((wB >> sh) & 1u)) v0 = -1e9f;
                if (!((wB >> (sh + 1)) & 1u)) v1 = -1e9f;
                sc[nb][2] = v0; sc[nb][3] = v1;
                mx1 = fmaxf(mx1, fmaxf(v0, v1));
            }
        }
        mx0 = fmaxf(mx0, __shfl_xor_sync(0xffffffffu, mx0, 1));
        mx0 = fmaxf(mx0, __shfl_xor_sync(0xffffffffu, mx0, 2));
        mx1 = fmaxf(mx1, __shfl_xor_sync(0xffffffffu, mx1, 1));
        mx1 = fmaxf(mx1, __shfl_xor_sync(0xffffffffu, mx1, 2));

        float nm0 = fmaxf(m0, mx0), nm1 = fmaxf(m1, mx1);
        float al0 = __expf(m0 - nm0), al1 = __expf(m1 - nm1);
        m0 = nm0; m1 = nm1;

        float s0 = 0.f, s1 = 0.f;
        #pragma unroll
        for (int nb = 0; nb < 8; nb++) {
            float p0 = __expf(sc[nb][0] - nm0);
            float p1 = __expf(sc[nb][1] - nm0);
            float p2 = __expf(sc[nb][2] - nm1);
            float p3 = __expf(sc[nb][3] - nm1);
            sc[nb][0] = p0; sc[nb][1] = p1; sc[nb][2] = p2; sc[nb][3] = p3;
            s0 += p0 + p1; s1 += p2 + p3;
        }
        s0 += __shfl_xor_sync(0xffffffffu, s0, 1);
        s0 += __shfl_xor_sync(0xffffffffu, s0, 2);
        s1 += __shfl_xor_sync(0xffffffffu, s1, 1);
        s1 += __shfl_xor_sync(0xffffffffu, s1, 2);
        l0 = l0 * al0 + s0; l1 = l1 * al1 + s1;

        #pragma unroll
        for (int db = 0; db < 8; db++) {
            o[db][0] *= al0; o[db][1] *= al0;
            o[db][2] *= al1; o[db][3] *= al1;
        }

        #pragma unroll
        for (int kc = 0; kc < 8; kc++) {
            float x0 = __shfl_sync(0xffffffffu, sc[kc][0], lolane);
            float x1 = __shfl_sync(0xffffffffu, sc[kc][1], lolane);
            float x2 = __shfl_sync(0xffffffffu, sc[kc][2], lolane);
            float x3 = __shfl_sync(0xffffffffu, sc[kc][3], lolane);
            float y0 = __shfl_sync(0xffffffffu, sc[kc][0], lolane + 2);
            float y1 = __shfl_sync(0xffffffffu, sc[kc][1], lolane + 2);
            float y2 = __shfl_sync(0xffffffffu, sc[kc][2], lolane + 2);
            float y3 = __shfl_sync(0xffffffffu, sc[kc][3], lolane + 2);
            unsigned A0 = __float_as_uint(cvt_tf32(oddq ? x1 : x0));
            unsigned A1 = __float_as_uint(cvt_tf32(oddq ? x3 : x2));
            unsigned A2 = __float_as_uint(cvt_tf32(oddq ? y1 : y0));
            unsigned A3 = __float_as_uint(cvt_tf32(oddq ? y3 : y2));
            #pragma unroll
            for (int db = 0; db < 8; db++) {
                unsigned B0 = __float_as_uint(Vs[(kc * 8 + q) * 72 + db * 8 + g]);
                unsigned B1 = __float_as_uint(Vs[(kc * 8 + q + 4) * 72 + db * 8 + g]);
                mma_tf32(o[db][0], o[db][1], o[db][2], o[db][3],
                         A0, A1, A2, A3, B0, B1);
            }
        }
    }

    float inv0 = 1.0f / l0, inv1 = 1.0f / l1;
    __syncthreads();
    #pragma unroll
    for (int db = 0; db < 8; db++) {
        int d = db * 8 + 2 * q;
        Qs[(d    ) * 68 + r0    ] = o[db][0] * inv0;
        Qs[(d + 1) * 68 + r0    ] = o[db][1] * inv0;
        Qs[(d    ) * 68 + r0 + 8] = o[db][2] * inv1;
        Qs[(d + 1) * 68 + r0 + 8] = o[db][3] * inv1;
    }
    __syncthreads();
    float* Og = g_O + ((size_t)(b * CCH + h * HD)) * LSP + i0;
    #pragma unroll
    for (int it = 0; it < 8; it++) {
        int idx = tid + it * 128;
        int d = idx >> 4, seg = (idx & 15) * 4;
        *(float4*)&Og[(size_t)d * LSP + seg] = *(float4*)&Qs[d * 68 + seg];
    }
}

// ---------------- LayerNorm over channels ----------------
__global__ void ln_kernel(const float* __restrict__ gamma, const float* __restrict__ beta,
                          float* __restrict__ out)
{
    int blk = blockIdx.x;
    int b  = blk / (LSP / 32);
    int l0 = (blk % (LSP / 32)) * 32;
    int lt = threadIdx.x & 31;
    int cg = threadIdx.x >> 5;
    const float* Yb = g_Y + (size_t)b * CCH * LSP;

    float sum = 0.f, sq = 0.f;
    for (int c = cg; c < CCH; c += 8) {
        float v = Yb[(size_t)c * LSP + l0 + lt];
        sum += v; sq += v * v;
    }
    __shared__ float ss[8][32], s2[8][32];
    __shared__ float mu[32], rs[32];
    ss[cg][lt] = sum; s2[cg][lt] = sq;
    __syncthreads();
    if (threadIdx.x < 32) {
        float s = 0.f, qq = 0.f;
        #pragma unroll
        for (int gg = 0; gg < 8; gg++) { s += ss[gg][threadIdx.x]; qq += s2[gg][threadIdx.x]; }
        float m = s * (1.0f / CCH);
        float var = qq * (1.0f / CCH) - m * m;
        mu[threadIdx.x] = m;
        rs[threadIdx.x] = rsqrtf(var + LN_EPS);
    }
    __syncthreads();
    float m = mu[lt], r = rs[lt];
    float* ob = out + (size_t)b * CCH * LSP;
    for (int c = cg; c < CCH; c += 8) {
        size_t off = (size_t)c * LSP + l0 + lt;
        ob[off] = (Yb[off] - m) * r * gamma[c] + beta[c];
    }
}

// ---------------- launch ----------------
extern "C" void kernel_launch(void* const* d_in, const int* in_sizes, int n_in,
                              void* d_out, int out_size)
{
    const float* x    = (const float*)d_in[0];
    const void*  mask =                d_in[1];
    const float* pos  = (const float*)d_in[2];
    const float* Wq   = (const float*)d_in[3];
    const float* bq   = (const float*)d_in[4];
    const float* Wk   = (const float*)d_in[5];
    const float* bk   = (const float*)d_in[6];
    const float* Wv   = (const float*)d_in[7];
    const float* bv   = (const float*)d_in[8];
    const float* Wo   = (const float*)d_in[9];
    const float* bo   = (const float*)d_in[10];
    const float* rel  = (const float*)d_in[11];
    const float* gam  = (const float*)d_in[12];
    const float* bet  = (const float*)d_in[13];
    float* out = (float*)d_out;

    const int attn_smem = (64 * 68 + 64 * 68 + 64 * 72 + 68) * 4;  // 53520 B
    cudaFuncSetAttribute(attn_kernel, cudaFuncAttributeMaxDynamicSharedMemorySize, attn_smem);

    detect_mask_kernel<<<1, 256>>>((const unsigned*)mask);
    {
        const int NW = NHEADS * LSP * LWORDS;
        pack_mask_kernel<<<(NW + 255) / 256, 256>>>(mask);
    }
    qkv_gemm_kernel<<<dim3(LSP / 256, CCH / 64, BATCH * 3), 256>>>(
        x, pos, Wq, bq, Wk, bk, Wv, bv);
    attn_kernel<<<dim3(LSP / 64, BATCH * NHEADS), 128, attn_smem>>>(rel);
    out_gemm_kernel<<<dim3(LSP / 256, CCH / 64, BATCH), 256>>>(x, Wo, bo);
    ln_kernel<<<BATCH * LSP / 32, 256>>>(gam, bet, out);
}

// round 5
// speedup vs baseline: 2.3825x; 1.0779x over previous
#include <cuda_runtime.h>
#include <stdint.h>
#include <math.h>

#define NHEADS 8
#define HD     64
#define CCH    512
#define LSP    2304            // 48*48
#define BATCH  2
#define LWORDS (LSP/32)        // 72
#define LN_EPS 1e-5f

// ---------------- scratch ----------------
__device__ float g_Q[BATCH*NHEADS*LSP*HD];   // (b,h,l,d)
__device__ float g_K[BATCH*NHEADS*LSP*HD];
__device__ float g_V[BATCH*NHEADS*LSP*HD];
__device__ float g_O[BATCH*CCH*LSP];         // attention out, (b,c,l)
__device__ float g_Y[BATCH*CCH*LSP];         // residual + Wo conv, (b,c,l)
__device__ __align__(16) unsigned g_maskbits[NHEADS*LSP*LWORDS];
__device__ int g_mask_mode;

// ---------------- helpers ----------------
__device__ __forceinline__ float cvt_tf32(float x) {
    float r; asm("cvt.rna.tf32.f32 %0, %1;" : "=f"(r) : "f"(x)); return r;
}
__device__ __forceinline__ void mma_tf32(float& c0, float& c1, float& c2, float& c3,
                                         unsigned a0, unsigned a1, unsigned a2, unsigned a3,
                                         unsigned b0, unsigned b1) {
    asm volatile("mma.sync.aligned.m16n8k8.row.col.f32.tf32.tf32.f32 "
                 "{%0,%1,%2,%3},{%4,%5,%6,%7},{%8,%9},{%0,%1,%2,%3};"
                 : "+f"(c0), "+f"(c1), "+f"(c2), "+f"(c3)
                 : "r"(a0), "r"(a1), "r"(a2), "r"(a3), "r"(b0), "r"(b1));
}

// ---------------- mask dtype detection ----------------
__global__ void detect_mask_kernel(const unsigned* __restrict__ mw) {
    __shared__ int s_f32, s_big;
    if (threadIdx.x == 0) { s_f32 = 0; s_big = 0; }
    __syncthreads();
    int lf = 0, lb = 0;
    for (int i = threadIdx.x; i < 4096; i += blockDim.x) {
        unsigned w = mw[i];
        if (w == 0x3F800000u) lf++;
        else if (w > 1u) lb++;
    }
    atomicAdd(&s_f32, lf);
    atomicAdd(&s_big, lb);
    __syncthreads();
    if (threadIdx.x == 0)
        g_mask_mode = (s_f32 > 0) ? 1 : ((s_big > 0) ? 2 : 0);
}

// ---------------- mask bit-packing (warp-ballot) ----------------
__global__ void pack_mask_kernel(const void* __restrict__ mask) {
    const int NW = NHEADS * LSP * LWORDS;
    int lane = threadIdx.x & 31;
    int gw = (blockIdx.x * blockDim.x + threadIdx.x) >> 5;
    int nw = (gridDim.x * blockDim.x) >> 5;
    int mode = g_mask_mode;
    if (mode == 0) {
        const int* p = (const int*)mask;
        for (int w = gw; w < NW; w += nw) {
            unsigned bits = __ballot_sync(0xffffffffu, p[(size_t)w * 32 + lane] != 0);
            if (lane == 0) g_maskbits[w] = bits;
        }
    } else if (mode == 1) {
        const float* p = (const float*)mask;
        for (int w = gw; w < NW; w += nw) {
            unsigned bits = __ballot_sync(0xffffffffu, p[(size_t)w * 32 + lane] != 0.0f);
            if (lane == 0) g_maskbits[w] = bits;
        }
    } else {
        const unsigned char* p = (const unsigned char*)mask;
        for (int w = gw; w < NW; w += nw) {
            unsigned bits = __ballot_sync(0xffffffffu, p[(size_t)w * 32 + lane] != 0);
            if (lane == 0) g_maskbits[w] = bits;
        }
    }
}

// ============== tf32 tensor-core GEMM kernels ==============
#define GAPAD 20
#define GBPAD 264
#define GASZ (64*GAPAD)
#define GBSZ (16*GBPAD)

// ---------------- QKV projection (tf32 mma, transposed output) ----------------
__global__ __launch_bounds__(256, 2)
void qkv_gemm_kernel(const float* __restrict__ x, const float* __restrict__ pos,
                     const float* __restrict__ Wq, const float* __restrict__ bq,
                     const float* __restrict__ Wk, const float* __restrict__ bk,
                     const float* __restrict__ Wv, const float* __restrict__ bv)
{
    __shared__ float sm[2 * (GASZ + GBSZ)];

    int nt = blockIdx.x;
    int mt = blockIdx.y;
    int bz = blockIdx.z;
    int b = bz / 3, which = bz % 3;
    const float* W    = (which == 0) ? Wq : (which == 1) ? Wk : Wv;
    const float* bias = (which == 0) ? bq : (which == 1) ? bk : bv;
    float* Out        = (which == 0) ? g_Q : (which == 1) ? g_K : g_V;

    int n0 = nt * 256;
    const float* xb = x + (size_t)b * CCH * LSP;

    int tid = threadIdx.x;
    int w = tid >> 5, lane = tid & 31;
    int wm = w >> 2, wn = w & 3;
    int g = lane >> 2, q = lane & 3;

    int ar = tid >> 2, akq = (tid & 3) << 2;
    const float* Wrow = W + (size_t)(mt * 64 + ar) * CCH + akq;

    float acc[2][8][4];
    #pragma unroll
    for (int mi = 0; mi < 2; mi++)
        #pragma unroll
        for (int ni = 0; ni < 8; ni++)
            #pragma unroll
            for (int r = 0; r < 4; r++) acc[mi][ni][r] = 0.f;

    float4 aR; float4 bR[4];
    aR = *(const float4*)&Wrow[0];
    #pragma unroll
    for (int i = 0; i < 4; i++) {
        int idx = tid + i * 256;
        int kr = idx >> 6, nq = (idx & 63) << 2;
        size_t off = (size_t)kr * LSP + n0 + nq;
        float4 v = *(const float4*)&xb[off];
        float4 p = *(const float4*)&pos[off];
        v.x += p.x; v.y += p.y; v.z += p.z; v.w += p.w;
        bR[i] = v;
    }
    {
        float* as = sm;
        float* bs = sm + 2 * GASZ;
        as[ar * GAPAD + akq + 0] = cvt_tf32(aR.x);
        as[ar * GAPAD + akq + 1] = cvt_tf32(aR.y);
        as[ar * GAPAD + akq + 2] = cvt_tf32(aR.z);
        as[ar * GAPAD + akq + 3] = cvt_tf32(aR.w);
        #pragma unroll
        for (int i = 0; i < 4; i++) {
            int idx = tid + i * 256;
            int kr = idx >> 6, nq = (idx & 63) << 2;
            bs[kr * GBPAD + nq + 0] = cvt_tf32(bR[i].x);
            bs[kr * GBPAD + nq + 1] = cvt_tf32(bR[i].y);
            bs[kr * GBPAD + nq + 2] = cvt_tf32(bR[i].z);
            bs[kr * GBPAD + nq + 3] = cvt_tf32(bR[i].w);
        }
    }
    __syncthreads();

    int buf = 0;
    for (int kt = 0; kt < 32; kt++) {
        if (kt < 31) {
            int k0 = (kt + 1) * 16;
            aR = *(const float4*)&Wrow[k0];
            #pragma unroll
            for (int i = 0; i < 4; i++) {
                int idx = tid + i * 256;
                int kr = idx >> 6, nq = (idx & 63) << 2;
                size_t off = (size_t)(k0 + kr) * LSP + n0 + nq;
                float4 v = *(const float4*)&xb[off];
                float4 p = *(const float4*)&pos[off];
                v.x += p.x; v.y += p.y; v.z += p.z; v.w += p.w;
                bR[i] = v;
            }
        }
        const float* as = sm + buf * GASZ;
        const float* bs = sm + 2 * GASZ + buf * GBSZ;
        #pragma unroll
        for (int kc = 0; kc < 2; kc++) {
            unsigned Af[2][4];
            #pragma unroll
            for (int mi = 0; mi < 2; mi++) {
                int mr = wm * 32 + mi * 16;
                Af[mi][0] = __float_as_uint(as[(mr + g    ) * GAPAD + kc * 8 + q    ]);
                Af[mi][1] = __float_as_uint(as[(mr + g + 8) * GAPAD + kc * 8 + q    ]);
                Af[mi][2] = __float_as_uint(as[(mr + g    ) * GAPAD + kc * 8 + q + 4]);
                Af[mi][3] = __float_as_uint(as[(mr + g + 8) * GAPAD + kc * 8 + q + 4]);
            }
            #pragma unroll
            for (int ni = 0; ni < 8; ni++) {
                unsigned B0 = __float_as_uint(bs[(kc * 8 + q    ) * GBPAD + wn * 64 + ni * 8 + g]);
                unsigned B1 = __float_as_uint(bs[(kc * 8 + q + 4) * GBPAD + wn * 64 + ni * 8 + g]);
                mma_tf32(acc[0][ni][0], acc[0][ni][1], acc[0][ni][2], acc[0][ni][3],
                         Af[0][0], Af[0][1], Af[0][2], Af[0][3], B0, B1);
                mma_tf32(acc[1][ni][0], acc[1][ni][1], acc[1][ni][2], acc[1][ni][3],
                         Af[1][0], Af[1][1], Af[1][2], Af[1][3], B0, B1);
            }
        }
        if (kt < 31) {
            float* asn = sm + (buf ^ 1) * GASZ;
            float* bsn = sm + 2 * GASZ + (buf ^ 1) * GBSZ;
            asn[ar * GAPAD + akq + 0] = cvt_tf32(aR.x);
            asn[ar * GAPAD + akq + 1] = cvt_tf32(aR.y);
            asn[ar * GAPAD + akq + 2] = cvt_tf32(aR.z);
            asn[ar * GAPAD + akq + 3] = cvt_tf32(aR.w);
            #pragma unroll
            for (int i = 0; i < 4; i++) {
                int idx = tid + i * 256;
                int kr = idx >> 6, nq = (idx & 63) << 2;
                bsn[kr * GBPAD + nq + 0] = cvt_tf32(bR[i].x);
                bsn[kr * GBPAD + nq + 1] = cvt_tf32(bR[i].y);
                bsn[kr * GBPAD + nq + 2] = cvt_tf32(bR[i].z);
                bsn[kr * GBPAD + nq + 3] = cvt_tf32(bR[i].w);
            }
        }
        __syncthreads();
        buf ^= 1;
    }

    float bb[2][2];
    #pragma unroll
    for (int mi = 0; mi < 2; mi++) {
        bb[mi][0] = bias[mt * 64 + wm * 32 + mi * 16 + g];
        bb[mi][1] = bias[mt * 64 + wm * 32 + mi * 16 + g + 8];
    }
    float* Cs = sm;
    float* ob = Out + ((size_t)(b * NHEADS + mt) * LSP + n0) * HD;
    #pragma unroll
    for (int chunk = 0; chunk < 4; chunk++) {
        if (wn == chunk) {
            #pragma unroll
            for (int mi = 0; mi < 2; mi++) {
                int m0 = wm * 32 + mi * 16 + g;
                #pragma unroll
                for (int ni = 0; ni < 8; ni++) {
                    int col = ni * 8 + 2 * q;
                    Cs[(col    ) * 68 + m0    ] = acc[mi][ni][0] + bb[mi][0];
                    Cs[(col + 1) * 68 + m0    ] = acc[mi][ni][1] + bb[mi][0];
                    Cs[(col    ) * 68 + m0 + 8] = acc[mi][ni][2] + bb[mi][1];
                    Cs[(col + 1) * 68 + m0 + 8] = acc[mi][ni][3] + bb[mi][1];
                }
            }
        }
        __syncthreads();
        #pragma unroll
        for (int i = 0; i < 4; i++) {
            int idx = tid + i * 256;
            int l = idx >> 4, mseg = (idx & 15) << 2;
            *(float4*)&ob[(size_t)(chunk * 64 + l) * HD + mseg] = *(float4*)&Cs[l * 68 + mseg];
        }
        __syncthreads();
    }
}

// ---------------- output projection (tf32 mma) + bias + residual ----------------
__global__ __launch_bounds__(256, 2)
void out_gemm_kernel(const float* __restrict__ x,
                     const float* __restrict__ Wo, const float* __restrict__ bo)
{
    __shared__ float sm[2 * (GASZ + GBSZ)];

    int nt = blockIdx.x;
    int mt = blockIdx.y;
    int b  = blockIdx.z;
    int n0 = nt * 256;
    const float* Ob = g_O + (size_t)b * CCH * LSP;

    int tid = threadIdx.x;
    int w = tid >> 5, lane = tid & 31;
    int wm = w >> 2, wn = w & 3;
    int g = lane >> 2, q = lane & 3;

    int ar = tid >> 2, akq = (tid & 3) << 2;
    const float* Wrow = Wo + (size_t)(mt * 64 + ar) * CCH + akq;

    float acc[2][8][4];
    #pragma unroll
    for (int mi = 0; mi < 2; mi++)
        #pragma unroll
        for (int ni = 0; ni < 8; ni++)
            #pragma unroll
            for (int r = 0; r < 4; r++) acc[mi][ni][r] = 0.f;

    float4 aR; float4 bR[4];
    aR = *(const float4*)&Wrow[0];
    #pragma unroll
    for (int i = 0; i < 4; i++) {
        int idx = tid + i * 256;
        int kr = idx >> 6, nq = (idx & 63) << 2;
        bR[i] = *(const float4*)&Ob[(size_t)kr * LSP + n0 + nq];
    }
    {
        float* as = sm;
        float* bs = sm + 2 * GASZ;
        as[ar * GAPAD + akq + 0] = cvt_tf32(aR.x);
        as[ar * GAPAD + akq + 1] = cvt_tf32(aR.y);
        as[ar * GAPAD + akq + 2] = cvt_tf32(aR.z);
        as[ar * GAPAD + akq + 3] = cvt_tf32(aR.w);
        #pragma unroll
        for (int i = 0; i < 4; i++) {
            int idx = tid + i * 256;
            int kr = idx >> 6, nq = (idx & 63) << 2;
            bs[kr * GBPAD + nq + 0] = cvt_tf32(bR[i].x);
            bs[kr * GBPAD + nq + 1] = cvt_tf32(bR[i].y);
            bs[kr * GBPAD + nq + 2] = cvt_tf32(bR[i].z);
            bs[kr * GBPAD + nq + 3] = cvt_tf32(bR[i].w);
        }
    }
    __syncthreads();

    int buf = 0;
    for (int kt = 0; kt < 32; kt++) {
        if (kt < 31) {
            int k0 = (kt + 1) * 16;
            aR = *(const float4*)&Wrow[k0];
            #pragma unroll
            for (int i = 0; i < 4; i++) {
                int idx = tid + i * 256;
                int kr = idx >> 6, nq = (idx & 63) << 2;
                bR[i] = *(const float4*)&Ob[(size_t)(k0 + kr) * LSP + n0 + nq];
            }
        }
        const float* as = sm + buf * GASZ;
        const float* bs = sm + 2 * GASZ + buf * GBSZ;
        #pragma unroll
        for (int kc = 0; kc < 2; kc++) {
            unsigned Af[2][4];
            #pragma unroll
            for (int mi = 0; mi < 2; mi++) {
                int mr = wm * 32 + mi * 16;
                Af[mi][0] = __float_as_uint(as[(mr + g    ) * GAPAD + kc * 8 + q    ]);
                Af[mi][1] = __float_as_uint(as[(mr + g + 8) * GAPAD + kc * 8 + q    ]);
                Af[mi][2] = __float_as_uint(as[(mr + g    ) * GAPAD + kc * 8 + q + 4]);
                Af[mi][3] = __float_as_uint(as[(mr + g + 8) * GAPAD + kc * 8 + q + 4]);
            }
            #pragma unroll
            for (int ni = 0; ni < 8; ni++) {
                unsigned B0 = __float_as_uint(bs[(kc * 8 + q    ) * GBPAD + wn * 64 + ni * 8 + g]);
                unsigned B1 = __float_as_uint(bs[(kc * 8 + q + 4) * GBPAD + wn * 64 + ni * 8 + g]);
                mma_tf32(acc[0][ni][0], acc[0][ni][1], acc[0][ni][2], acc[0][ni][3],
                         Af[0][0], Af[0][1], Af[0][2], Af[0][3], B0, B1);
                mma_tf32(acc[1][ni][0], acc[1][ni][1], acc[1][ni][2], acc[1][ni][3],
                         Af[1][0], Af[1][1], Af[1][2], Af[1][3], B0, B1);
            }
        }
        if (kt < 31) {
            float* asn = sm + (buf ^ 1) * GASZ;
            float* bsn = sm + 2 * GASZ + (buf ^ 1) * GBSZ;
            asn[ar * GAPAD + akq + 0] = cvt_tf32(aR.x);
            asn[ar * GAPAD + akq + 1] = cvt_tf32(aR.y);
            asn[ar * GAPAD + akq + 2] = cvt_tf32(aR.z);
            asn[ar * GAPAD + akq + 3] = cvt_tf32(aR.w);
            #pragma unroll
            for (int i = 0; i < 4; i++) {
                int idx = tid + i * 256;
                int kr = idx >> 6, nq = (idx & 63) << 2;
                bsn[kr * GBPAD + nq + 0] = cvt_tf32(bR[i].x);
                bsn[kr * GBPAD + nq + 1] = cvt_tf32(bR[i].y);
                bsn[kr * GBPAD + nq + 2] = cvt_tf32(bR[i].z);
                bsn[kr * GBPAD + nq + 3] = cvt_tf32(bR[i].w);
            }
        }
        __syncthreads();
        buf ^= 1;
    }

    #pragma unroll
    for (int mi = 0; mi < 2; mi++) {
        int m0 = mt * 64 + wm * 32 + mi * 16 + g;
        float b0v = bo[m0], b1v = bo[m0 + 8];
        #pragma unroll
        for (int ni = 0; ni < 8; ni++) {
            int n = n0 + wn * 64 + ni * 8 + 2 * q;
            size_t off0 = ((size_t)b * CCH + m0) * LSP + n;
            size_t off1 = off0 + (size_t)8 * LSP;
            float2 xv0 = *(const float2*)&x[off0];
            float2 xv1 = *(const float2*)&x[off1];
            float2 r0 = { acc[mi][ni][0] + b0v + xv0.x, acc[mi][ni][1] + b0v + xv0.y };
            float2 r1 = { acc[mi][ni][2] + b1v + xv1.x, acc[mi][ni][3] + b1v + xv1.y };
            *(float2*)&g_Y[off0] = r0;
            *(float2*)&g_Y[off1] = r1;
        }
    }
}

// ---------------- fused flash attention: mma.sync tf32, no-max softmax -------
__global__ __launch_bounds__(128, 3)
void attn_kernel(const float* __restrict__ rel_table)
{
    extern __shared__ float smx[];
    float* Qs = smx;              // [64][68]
    float* Ks = Qs + 64 * 68;     // [64][68]
    float* Vs = Ks + 64 * 68;     // [64][72]
    float* relrow = Vs + 64 * 72; // 68

    int tid = threadIdx.x;
    int w = tid >> 5, lane = tid & 31;
    int g = lane >> 2, q = lane & 3;
    int bh = blockIdx.y;
    int b = bh >> 3, h = bh & 7;
    int i0 = blockIdx.x * 64;

    const float* Qg = g_Q + (size_t)bh * LSP * HD;
    const float* Kg = g_K + (size_t)bh * LSP * HD;
    const float* Vg = g_V + (size_t)bh * LSP * HD;
    const unsigned* mbase = g_maskbits + (size_t)(h * LSP + i0) * LWORDS;

    if (tid < 65) relrow[tid] = rel_table[h * 65 + tid];

    #pragma unroll
    for (int it = 0; it < 8; it++) {
        int idx = tid + it * 128;
        int m = idx >> 4, dq = (idx & 15) * 4;
        float4 v = *(const float4*)&Qg[(size_t)(i0 + m) * HD + dq];
        v.x = cvt_tf32(v.x); v.y = cvt_tf32(v.y);
        v.z = cvt_tf32(v.z); v.w = cvt_tf32(v.w);
        *(float4*)&Qs[m * 68 + dq] = v;
    }

    const int r0 = 16 * w + g;
    const int iA = i0 + r0, iB = iA + 8;
    float o[8][4] = {};
    float l0 = 0.f, l1 = 0.f;
    const float scale = 0.125f;
    const int lolane = (lane & ~3) | (q >> 1);
    const bool oddq = (q & 1);

    for (int jt = 0; jt < 36; jt++) {
        int j0 = jt * 64;
        __syncthreads();
        #pragma unroll
        for (int it = 0; it < 8; it++) {
            int idx = tid + it * 128;
            int n = idx >> 4, dq = (idx & 15) * 4;
            float4 kv = *(const float4*)&Kg[(size_t)(j0 + n) * HD + dq];
            kv.x = cvt_tf32(kv.x); kv.y = cvt_tf32(kv.y);
            kv.z = cvt_tf32(kv.z); kv.w = cvt_tf32(kv.w);
            *(float4*)&Ks[n * 68 + dq] = kv;
            float4 vv = *(const float4*)&Vg[(size_t)(j0 + n) * HD + dq];
            vv.x = cvt_tf32(vv.x); vv.y = cvt_tf32(vv.y);
            vv.z = cvt_tf32(vv.z); vv.w = cvt_tf32(vv.w);
            *(float4*)&Vs[n * 72 + dq] = vv;
        }
        __syncthreads();

        uint2 mwA = *(const uint2*)&mbase[(size_t)r0 * LWORDS + jt * 2];
        uint2 mwB = *(const uint2*)&mbase[(size_t)(r0 + 8) * LWORDS + jt * 2];

        // ---- S = Q K^T ----
        float sc[8][4];
        #pragma unroll
        for (int nb = 0; nb < 8; nb++)
            #pragma unroll
            for (int r = 0; r < 4; r++) sc[nb][r] = 0.f;

        #pragma unroll
        for (int kc = 0; kc < 8; kc++) {
            unsigned A0 = __float_as_uint(Qs[r0 * 68 + kc * 8 + q]);
            unsigned A1 = __float_as_uint(Qs[(r0 + 8) * 68 + kc * 8 + q]);
            unsigned A2 = __float_as_uint(Qs[r0 * 68 + kc * 8 + q + 4]);
            unsigned A3 = __float_as_uint(Qs[(r0 + 8) * 68 + kc * 8 + q + 4]);
            #pragma unroll
            for (int nb = 0; nb < 8; nb++) {
                unsigned B0 = __float_as_uint(Ks[(nb * 8 + g) * 68 + kc * 8 + q]);
                unsigned B1 = __float_as_uint(Ks[(nb * 8 + g) * 68 + kc * 8 + q + 4]);
                mma_tf32(sc[nb][0], sc[nb][1], sc[nb][2], sc[nb][3],
                         A0, A1, A2, A3, B0, B1);
            }
        }

        // ---- scale + rel bias + mask -> p = exp(sv) (no running max) ----
        #pragma unroll
        for (int nb = 0; nb < 8; nb++) {
            int colt = nb * 8 + 2 * q;
            int jl = j0 + colt;
            unsigned wA = (colt >= 32) ? mwA.y : mwA.x;
            unsigned wB = (colt >= 32) ? mwB.y : mwB.x;
            int sh = colt & 31;
            {
                int d0 = min(max(iA - jl, -32), 32);
                int d1 = min(max(iA - jl - 1, -32), 32);
                float p0 = ((wA >> sh) & 1u)       ? __expf(sc[nb][0] * scale + relrow[d0 + 32]) : 0.f;
                float p1 = ((wA >> (sh + 1)) & 1u) ? __expf(sc[nb][1] * scale + relrow[d1 + 32]) : 0.f;
                sc[nb][0] = p0; sc[nb][1] = p1;
                l0 += p0 + p1;
            }
            {
                int d0 = min(max(iB - jl, -32), 32);
                int d1 = min(max(iB - jl - 1, -32), 32);
                float p0 = ((wB >> sh) & 1u)       ? __expf(sc[nb][2] * scale + relrow[d0 + 32]) : 0.f;
                float p1 = ((wB >> (sh + 1)) & 1u) ? __expf(sc[nb][3] * scale + relrow[d1 + 32]) : 0.f;
                sc[nb][2] = p0; sc[nb][3] = p1;
                l1 += p0 + p1;
            }
        }

        // ---- O += P V  (P C-frags -> A-frags via quad shuffles) ----
        #pragma unroll
        for (int kc = 0; kc < 8; kc++) {
            float x0 = __shfl_sync(0xffffffffu, sc[kc][0], lolane);
            float x1 = __shfl_sync(0xffffffffu, sc[kc][1], lolane);
            float x2 = __shfl_sync(0xffffffffu, sc[kc][2], lolane);
            float x3 = __shfl_sync(0xffffffffu, sc[kc][3], lolane);
            float y0 = __shfl_sync(0xffffffffu, sc[kc][0], lolane + 2);
            float y1 = __shfl_sync(0xffffffffu, sc[kc][1], lolane + 2);
            float y2 = __shfl_sync(0xffffffffu, sc[kc][2], lolane + 2);
            float y3 = __shfl_sync(0xffffffffu, sc[kc][3], lolane + 2);
            unsigned A0 = __float_as_uint(cvt_tf32(oddq ? x1 : x0));
            unsigned A1 = __float_as_uint(cvt_tf32(oddq ? x3 : x2));
            unsigned A2 = __float_as_uint(cvt_tf32(oddq ? y1 : y0));
            unsigned A3 = __float_as_uint(cvt_tf32(oddq ? y3 : y2));
            #pragma unroll
            for (int db = 0; db < 8; db++) {
                unsigned B0 = __float_as_uint(Vs[(kc * 8 + q) * 72 + db * 8 + g]);
                unsigned B1 = __float_as_uint(Vs[(kc * 8 + q + 4) * 72 + db * 8 + g]);
                mma_tf32(o[db][0], o[db][1], o[db][2], o[db][3],
                         A0, A1, A2, A3, B0, B1);
            }
        }
    }

    // ---- final row-sum reduction (over q quad) and normalize ----
    l0 += __shfl_xor_sync(0xffffffffu, l0, 1);
    l0 += __shfl_xor_sync(0xffffffffu, l0, 2);
    l1 += __shfl_xor_sync(0xffffffffu, l1, 1);
    l1 += __shfl_xor_sync(0xffffffffu, l1, 2);
    float inv0 = 1.0f / l0, inv1 = 1.0f / l1;

    __syncthreads();
    #pragma unroll
    for (int db = 0; db < 8; db++) {
        int d = db * 8 + 2 * q;
        Qs[(d    ) * 68 + r0    ] = o[db][0] * inv0;
        Qs[(d + 1) * 68 + r0    ] = o[db][1] * inv0;
        Qs[(d    ) * 68 + r0 + 8] = o[db][2] * inv1;
        Qs[(d + 1) * 68 + r0 + 8] = o[db][3] * inv1;
    }
    __syncthreads();
    float* Og = g_O + ((size_t)(b * CCH + h * HD)) * LSP + i0;
    #pragma unroll
    for (int it = 0; it < 8; it++) {
        int idx = tid + it * 128;
        int d = idx >> 4, seg = (idx & 15) * 4;
        *(float4*)&Og[(size_t)d * LSP + seg] = *(float4*)&Qs[d * 68 + seg];
    }
}

// ---------------- LayerNorm over channels ----------------
__global__ void ln_kernel(const float* __restrict__ gamma, const float* __restrict__ beta,
                          float* __restrict__ out)
{
    int blk = blockIdx.x;
    int b  = blk / (LSP / 32);
    int l0 = (blk % (LSP / 32)) * 32;
    int lt = threadIdx.x & 31;
    int cg = threadIdx.x >> 5;
    const float* Yb = g_Y + (size_t)b * CCH * LSP;

    float sum = 0.f, sq = 0.f;
    for (int c = cg; c < CCH; c += 8) {
        float v = Yb[(size_t)c * LSP + l0 + lt];
        sum += v; sq += v * v;
    }
    __shared__ float ss[8][32], s2[8][32];
    __shared__ float mu[32], rs[32];
    ss[cg][lt] = sum; s2[cg][lt] = sq;
    __syncthreads();
    if (threadIdx.x < 32) {
        float s = 0.f, qq = 0.f;
        #pragma unroll
        for (int gg = 0; gg < 8; gg++) { s += ss[gg][threadIdx.x]; qq += s2[gg][threadIdx.x]; }
        float m = s * (1.0f / CCH);
        float var = qq * (1.0f / CCH) - m * m;
        mu[threadIdx.x] = m;
        rs[threadIdx.x] = rsqrtf(var + LN_EPS);
    }
    __syncthreads();
    float m = mu[lt], r = rs[lt];
    float* ob = out + (size_t)b * CCH * LSP;
    for (int c = cg; c < CCH; c += 8) {
        size_t off = (size_t)c * LSP + l0 + lt;
        ob[off] = (Yb[off] - m) * r * gamma[c] + beta[c];
    }
}

// ---------------- launch ----------------
extern "C" void kernel_launch(void* const* d_in, const int* in_sizes, int n_in,
                              void* d_out, int out_size)
{
    const float* x    = (const float*)d_in[0];
    const void*  mask =                d_in[1];
    const float* pos  = (const float*)d_in[2];
    const float* Wq   = (const float*)d_in[3];
    const float* bq   = (const float*)d_in[4];
    const float* Wk   = (const float*)d_in[5];
    const float* bk   = (const float*)d_in[6];
    const float* Wv   = (const float*)d_in[7];
    const float* bv   = (const float*)d_in[8];
    const float* Wo   = (const float*)d_in[9];
    const float* bo   = (const float*)d_in[10];
    const float* rel  = (const float*)d_in[11];
    const float* gam  = (const float*)d_in[12];
    const float* bet  = (const float*)d_in[13];
    float* out = (float*)d_out;

    const int attn_smem = (64 * 68 + 64 * 68 + 64 * 72 + 68) * 4;  // 53520 B
    cudaFuncSetAttribute(attn_kernel, cudaFuncAttributeMaxDynamicSharedMemorySize, attn_smem);

    detect_mask_kernel<<<1, 256>>>((const unsigned*)mask);
    pack_mask_kernel<<<1184, 256>>>(mask);
    qkv_gemm_kernel<<<dim3(LSP / 256, CCH / 64, BATCH * 3), 256>>>(
        x, pos, Wq, bq, Wk, bk, Wv, bv);
    attn_kernel<<<dim3(LSP / 64, BATCH * NHEADS), 128, attn_smem>>>(rel);
    out_gemm_kernel<<<dim3(LSP / 256, CCH / 64, BATCH), 256>>>(x, Wo, bo);
    ln_kernel<<<BATCH * LSP / 32, 256>>>(gam, bet, out);
}